// round 8
// baseline (speedup 1.0000x reference)
#include <cuda_runtime.h>
#include <cstdint>
#include <math.h>

#define NN 50000
#define EE 400000
#define EPP 40000
#define FF 64
#define EDD 32
#define HH 128
#define LL 2

// ---------------- scratch (device globals; no allocation allowed) ----------------
__device__ float g_x[NN * HH];
__device__ float g_ea[EE * HH];
__device__ float g_upd[EE * HH];
__device__ float g_lin[NN * HH];
__device__ float g_s1[NN * HH];   // becomes mean after finalize
__device__ float g_s2[NN * HH];   // becomes std after finalize
__device__ float g_mn[NN * HH];
__device__ float g_mx[NN * HH];
__device__ float g_cw[1664 * 128];      // composite fp32 weights
__device__ float g_cb[HH];              // composite bias (pre)
__device__ float g_cb2[HH];             // composite bias (post)
__device__ float2 g_wt[(1664 / 16) * 1024];   // fragment-ordered tf32 weights
__device__ int   g_deg[NN];
__device__ float g_amp[NN];
__device__ float g_att[NN];
__device__ float g_bnsum[HH];
__device__ float g_bnsq[HH];
__device__ float g_bnmu[HH];
__device__ float g_bnrstd[HH];

// ---------------- helpers ----------------
__device__ __forceinline__ uint32_t smem_u32(const void* p) {
    uint32_t a;
    asm("{ .reg .u64 t; cvta.to.shared.u64 t, %1; cvt.u32.u64 %0, t; }" : "=r"(a) : "l"(p));
    return a;
}
__device__ __forceinline__ uint32_t f2tf32(float x) {
    uint32_t r; asm("cvt.rn.tf32.f32 %0, %1;" : "=r"(r) : "f"(x)); return r;
}
__device__ __forceinline__ void cp16(uint32_t sdst, const void* gsrc, bool full) {
    int sz = full ? 16 : 0;
    asm volatile("cp.async.cg.shared.global [%0], [%1], 16, %2;"
                 :: "r"(sdst), "l"(gsrc), "r"(sz) : "memory");
}
__device__ __forceinline__ void cp_commit() {
    asm volatile("cp.async.commit_group;" ::: "memory");
}
__device__ __forceinline__ void mma_tf32(float c[4], const uint32_t a[4], const uint32_t b[2]) {
    asm volatile(
        "mma.sync.aligned.m16n8k8.row.col.f32.tf32.tf32.f32 "
        "{%0,%1,%2,%3}, {%4,%5,%6,%7}, {%8,%9}, {%0,%1,%2,%3};\n"
        : "+f"(c[0]), "+f"(c[1]), "+f"(c[2]), "+f"(c[3])
        : "r"(a[0]), "r"(a[1]), "r"(a[2]), "r"(a[3]), "r"(b[0]), "r"(b[1]));
}

// ---------------- atomic float min/max ----------------
__device__ __forceinline__ void atomicMaxF(float* a, float v) {
    if (v >= 0.f) atomicMax((int*)a, __float_as_int(v));
    else          atomicMin((unsigned int*)a, __float_as_uint(v));
}
__device__ __forceinline__ void atomicMinF(float* a, float v) {
    if (v >= 0.f) atomicMin((int*)a, __float_as_int(v));
    else          atomicMax((unsigned int*)a, __float_as_uint(v));
}

// ---------------- A-tile loaders: ptr4(r,k) -> gmem pointer to 4 floats ----------------
struct PlainLd {
    const float* __restrict__ A; int K;
    static constexpr bool scaled = false;
    __device__ __forceinline__ const float* ptr4(int r, int k) const {
        return A + (long)r * K + k;
    }
    __device__ __forceinline__ float rowscale(int, int) const { return 1.f; }
};
struct GatherLd {  // [x[i0[r]], x[i1[r]], third[r]]  (each 128 wide)
    const float* __restrict__ x;
    const int* __restrict__ i0;
    const int* __restrict__ i1;
    const float* __restrict__ third;
    static constexpr bool scaled = false;
    __device__ __forceinline__ const float* ptr4(int r, int k) const {
        if (k < 128) return x + (long)i0[r] * 128 + k;
        if (k < 256) return x + (long)i1[r] * 128 + (k - 128);
        return third + (long)r * 128 + (k - 256);
    }
    __device__ __forceinline__ float rowscale(int, int) const { return 1.f; }
};
struct PostLd {  // [x, agg, agg*amp, agg*att]; agg = [mean, mn, mx, std]
    const float* __restrict__ x;
    const float* __restrict__ mean;
    const float* __restrict__ mn;
    const float* __restrict__ mx;
    const float* __restrict__ sd;
    const float* __restrict__ amp;
    const float* __restrict__ att;
    static constexpr bool scaled = true;
    __device__ __forceinline__ const float* ptr4(int r, int k) const {
        if (k < 128) return x + (long)r * 128 + k;
        int rem = (k - 128) & 511;
        int a   = rem >> 7;       // 0 mean, 1 mn, 2 mx, 3 std
        int c   = rem & 127;
        const float* base = (a == 0) ? mean : (a == 1) ? mn : (a == 2) ? mx : sd;
        return base + (long)r * 128 + c;
    }
    __device__ __forceinline__ float rowscale(int r, int k) const {
        if (k < 128) return 1.f;
        int grp = (k - 128) >> 9;   // 0: raw, 1: *amp, 2: *att
        return (grp == 1) ? amp[r] : (grp == 2) ? att[r] : 1.f;
    }
};

// ---------------- epilogues ----------------
struct StoreEp {
    float* __restrict__ o;
    __device__ __forceinline__ void pair(int r, int c, float v0, float v1) const {
        *(float2*)(o + (long)r * 128 + c) = make_float2(v0, v1);
    }
};
struct ReluEp {
    float* __restrict__ o;
    __device__ __forceinline__ void pair(int r, int c, float v0, float v1) const {
        *(float2*)(o + (long)r * 128 + c) = make_float2(fmaxf(v0, 0.f), fmaxf(v1, 0.f));
    }
};
struct EaEp {  // ea += v/2
    float* __restrict__ ea;
    __device__ __forceinline__ void pair(int r, int c, float v0, float v1) const {
        float2* p = (float2*)(ea + (long)r * 128 + c);
        float2 cur = *p;
        cur.x += 0.5f * v0; cur.y += 0.5f * v1;
        *p = cur;
    }
};
struct AggEp {  // segment sum / sumsq / min / max over dst
    float* __restrict__ s1; float* __restrict__ s2;
    float* __restrict__ mn; float* __restrict__ mx;
    const int* __restrict__ dst;
    __device__ __forceinline__ void one(long o, float v) const {
        atomicAdd(s1 + o, v);
        atomicAdd(s2 + o, v * v);
        atomicMaxF(mx + o, v);
        atomicMinF(mn + o, v);
    }
    __device__ __forceinline__ void pair(int r, int c, float v0, float v1) const {
        long o = (long)dst[r] * 128 + c;
        one(o, v0);
        one(o + 1, v1);
    }
};

// ---------------- weight prep: fragment-ordered tf32 ----------------
// Wp float2 index ((c*2 + s)*128 + n)*4 + t  <-  {W[16c+8s+t][n], W[16c+8s+t+4][n]}
__global__ void k_prep_w(const float* __restrict__ W, float2* __restrict__ Wp, int nf2) {
    int i = blockIdx.x * blockDim.x + threadIdx.x;
    if (i < nf2) {
        int t = i & 3, n = (i >> 2) & 127, s = (i >> 9) & 1, c = i >> 10;
        int k = c * 16 + s * 8 + t;
        Wp[i] = make_float2(__uint_as_float(f2tf32(W[(long)k * 128 + n])),
                            __uint_as_float(f2tf32(W[(long)(k + 4) * 128 + n])));
    }
}

// ---------------- composite weight builders (fp32) ----------------
// cw[0:256] = pW[0:256]; cw[256+k] = eW[k] @ pW[256:384]
__global__ void k_comp_pre(const float* __restrict__ eW, const float* __restrict__ pW,
                           float* __restrict__ cw) {
    int k = blockIdx.x, n = threadIdx.x;
    if (k < 256) {
        cw[(long)k * 128 + n] = pW[(long)k * 128 + n];
    } else {
        int kk = k - 256;
        float s = 0.f;
        for (int j = 0; j < 128; j++)
            s += eW[(long)kk * 128 + j] * pW[(long)(256 + j) * 128 + n];
        cw[(long)k * 128 + n] = s;
    }
}
__global__ void k_comp_pre_b(const float* __restrict__ eB, const float* __restrict__ pW,
                             const float* __restrict__ pB, float* __restrict__ cb) {
    int n = threadIdx.x;
    float s = pB[n];
    for (int j = 0; j < 128; j++) s += eB[j] * pW[(long)(256 + j) * 128 + n];
    cb[n] = s;
}
// cw[k] = poW[k] @ lW   (k in [0,1664))
__global__ void k_comp_post(const float* __restrict__ poW, const float* __restrict__ lW,
                            float* __restrict__ cw) {
    int k = blockIdx.x, n = threadIdx.x;
    float s = 0.f;
    for (int j = 0; j < 128; j++)
        s += poW[(long)k * 128 + j] * lW[(long)j * 128 + n];
    cw[(long)k * 128 + n] = s;
}
__global__ void k_comp_post_b(const float* __restrict__ poB, const float* __restrict__ lW,
                              const float* __restrict__ lB, float* __restrict__ cb) {
    int n = threadIdx.x;
    float s = lB[n];
    for (int j = 0; j < 128; j++) s += poB[j] * lW[(long)j * 128 + n];
    cb[n] = s;
}

// ---------------- tensor-core GEMM: out[M,128] = A[M,K] @ W[K,128] + b ----------------
// 128x128 CTA tile, 256 threads = 8 warps (4 M x 2 N), warp tile 32x64.
// mma.sync m16n8k8 tf32. K chunk = 16, 3-stage cp.async pipeline.
// Weights are pre-rounded tf32 in fragment order (k_prep_w).
#define KT 16
#define NSTG 3
#define AP 20    // A row pitch (floats)

template <typename Loader, typename Epi>
__global__ void __launch_bounds__(256, 2) gemm_mma(
    Loader ld, Epi ep,
    const float2* __restrict__ Wp, const float* __restrict__ bias,
    int M, int K)
{
    __shared__ float As[NSTG][128 * AP];
    __shared__ float Ws[NSTG][KT * 128];     // fragment-ordered chunk (8KB)
    const int tid  = threadIdx.x;
    const int lane = tid & 31;
    const int wid  = tid >> 5;
    const int wm   = wid & 3;        // warp row: 32 rows each
    const int wn   = wid >> 2;       // warp col: 64 cols each
    const int gid  = lane >> 2;      // 0..7
    const int tid4 = lane & 3;       // 0..3
    const int row0 = blockIdx.x * 128;

    const int sr0 = tid >> 2,  sq0 = tid & 3;
    const int sr1 = sr0 + 64;

    const uint32_t sA = smem_u32(&As[0][0]);
    const uint32_t sW = smem_u32(&Ws[0][0]);

    float acc[2][8][4];
#pragma unroll
    for (int mt = 0; mt < 2; mt++)
#pragma unroll
        for (int nt = 0; nt < 8; nt++)
#pragma unroll
            for (int i = 0; i < 4; i++) acc[mt][nt][i] = 0.f;

    const int nch = K / KT;

    auto stage = [&](int buf, int ch) {
        int k0 = ch * KT;
        uint32_t a_base = sA + buf * (128 * AP * 4);
        uint32_t w_base = sW + buf * (KT * 128 * 4);
        int g0 = row0 + sr0, g1 = row0 + sr1;
        bool v0 = g0 < M, v1 = g1 < M;
        cp16(a_base + (sr0 * AP + sq0 * 4) * 4, ld.ptr4(v0 ? g0 : 0, k0 + sq0 * 4), v0);
        cp16(a_base + (sr1 * AP + sq0 * 4) * 4, ld.ptr4(v1 ? g1 : 0, k0 + sq0 * 4), v1);
        const char* wsrc = (const char*)Wp + (long)ch * 8192;
        cp16(w_base + tid * 16,         wsrc + tid * 16,         true);
        cp16(w_base + (tid + 256) * 16, wsrc + (tid + 256) * 16, true);
        cp_commit();
    };

    int ncommit = 0;
    stage(0, 0); ncommit++;
    if (nch > 1) { stage(1, 1); ncommit++; }

    for (int ch = 0; ch < nch; ch++) {
        const int buf = ch % NSTG;
        const int k0 = ch * KT;
        if (ch + 2 < nch) { stage((ch + 2) % NSTG, ch + 2); ncommit++; }
        int allow = ncommit - ch - 1;
        if (allow >= 2)      asm volatile("cp.async.wait_group 2;" ::: "memory");
        else if (allow == 1) asm volatile("cp.async.wait_group 1;" ::: "memory");
        else                 asm volatile("cp.async.wait_group 0;" ::: "memory");
        __syncthreads();

        // per-chunk row scales (PostLd only)
        float rs[2][2];
        if constexpr (Loader::scaled) {
#pragma unroll
            for (int mt = 0; mt < 2; mt++) {
                int m0 = row0 + wm * 32 + mt * 16;
                int rA = m0 + gid, rB = m0 + 8 + gid;
                rs[mt][0] = ld.rowscale(rA < M ? rA : 0, k0);
                rs[mt][1] = ld.rowscale(rB < M ? rB : 0, k0);
            }
        }

        const float* Ab = &As[buf][0];
        const float2* Bb = (const float2*)&Ws[buf][0];
#pragma unroll
        for (int ks = 0; ks < KT; ks += 8) {
            const int s = ks >> 3;
            uint32_t a[2][4];
#pragma unroll
            for (int mt = 0; mt < 2; mt++) {
                int m0 = wm * 32 + mt * 16;
                float a0 = Ab[(m0 + gid) * AP + ks + tid4];
                float a1 = Ab[(m0 + 8 + gid) * AP + ks + tid4];
                float a2 = Ab[(m0 + gid) * AP + ks + tid4 + 4];
                float a3 = Ab[(m0 + 8 + gid) * AP + ks + tid4 + 4];
                if constexpr (Loader::scaled) {
                    a0 *= rs[mt][0]; a1 *= rs[mt][1];
                    a2 *= rs[mt][0]; a3 *= rs[mt][1];
                }
                a[mt][0] = f2tf32(a0); a[mt][1] = f2tf32(a1);
                a[mt][2] = f2tf32(a2); a[mt][3] = f2tf32(a3);
            }
            uint32_t b[8][2];
#pragma unroll
            for (int nt = 0; nt < 8; nt++) {
                int n = wn * 64 + nt * 8 + gid;
                float2 v = Bb[s * 512 + n * 4 + tid4];
                b[nt][0] = __float_as_uint(v.x);
                b[nt][1] = __float_as_uint(v.y);
            }
#pragma unroll
            for (int mt = 0; mt < 2; mt++)
#pragma unroll
                for (int nt = 0; nt < 8; nt++)
                    mma_tf32(acc[mt][nt], a[mt], b[nt]);
        }
        __syncthreads();
    }

    // epilogue
    float bv[8][2];
#pragma unroll
    for (int nt = 0; nt < 8; nt++) {
        int c = wn * 64 + nt * 8 + 2 * tid4;
        bv[nt][0] = bias[c];
        bv[nt][1] = bias[c + 1];
    }
#pragma unroll
    for (int mt = 0; mt < 2; mt++) {
        int rA = row0 + wm * 32 + mt * 16 + gid;
        int rB = rA + 8;
#pragma unroll
        for (int nt = 0; nt < 8; nt++) {
            int c = wn * 64 + nt * 8 + 2 * tid4;
            if (rA < M) ep.pair(rA, c, acc[mt][nt][0] + bv[nt][0], acc[mt][nt][1] + bv[nt][1]);
            if (rB < M) ep.pair(rB, c, acc[mt][nt][2] + bv[nt][0], acc[mt][nt][3] + bv[nt][1]);
        }
    }
}

// ---------------- small kernels ----------------
__global__ void k_zero_deg() {
    int i = blockIdx.x * blockDim.x + threadIdx.x;
    if (i < NN) g_deg[i] = 0;
}
__global__ void k_count_deg(const int* __restrict__ dst) {
    int e = blockIdx.x * blockDim.x + threadIdx.x;
    if (e < EE) atomicAdd(&g_deg[dst[e]], 1);
}
__global__ void k_amp_att(const float* __restrict__ adl) {
    int i = blockIdx.x * blockDim.x + threadIdx.x;
    if (i < NN) {
        float d = fmaxf((float)g_deg[i], 1.f);
        float lg = logf(d + 1.f);
        float a = adl[0];
        g_amp[i] = lg / a;
        g_att[i] = a / lg;
    }
}
__global__ void k_init_agg() {
    long i = (long)blockIdx.x * blockDim.x + threadIdx.x;
    if (i < (long)NN * HH) {
        g_s1[i] = 0.f;
        g_s2[i] = 0.f;
        g_mn[i] = __int_as_float(0x7f800000);   // +inf
        g_mx[i] = __int_as_float(0xff800000);   // -inf
    }
}
__global__ void k_zero_bn() {
    int c = threadIdx.x;
    g_bnsum[c] = 0.f;
    g_bnsq[c] = 0.f;
}
__global__ void k_fin_agg() {
    long i = (long)blockIdx.x * blockDim.x + threadIdx.x;
    if (i < (long)NN * HH) {
        int n = (int)(i >> 7);
        int d = g_deg[n];
        float degc = fmaxf((float)d, 1.f);
        float m = g_s1[i] / degc;
        float var = g_s2[i] / degc - m * m;
        g_s1[i] = m;
        g_s2[i] = sqrtf(fmaxf(var, 0.f) + 1e-5f);
        if (d == 0) { g_mn[i] = 0.f; g_mx[i] = 0.f; }
    }
}
__global__ void k_bn_stats(const float* __restrict__ o) {
    int c = threadIdx.x;           // 128 threads
    float s = 0.f, s2 = 0.f;
    for (int r = blockIdx.x; r < NN; r += gridDim.x) {
        float v = o[(long)r * 128 + c];
        s += v; s2 += v * v;
    }
    atomicAdd(&g_bnsum[c], s);
    atomicAdd(&g_bnsq[c], s2);
}
__global__ void k_bn_fin() {
    int c = threadIdx.x;
    float mu = g_bnsum[c] / (float)NN;
    float var = g_bnsq[c] / (float)NN - mu * mu;
    g_bnmu[c] = mu;
    g_bnrstd[c] = rsqrtf(var + 1e-5f);
}
__global__ void k_apply(const float* __restrict__ bng, const float* __restrict__ bnb,
                        float* __restrict__ xout) {
    long i = (long)blockIdx.x * blockDim.x + threadIdx.x;
    if (i < (long)NN * HH) {
        int c = (int)(i & 127);
        float v = bng[c] * (g_lin[i] - g_bnmu[c]) * g_bnrstd[c] + bnb[c];
        float nx = (g_x[i] + fmaxf(v, 0.f)) * 0.5f;
        g_x[i] = nx;
        if (xout) xout[i] = nx;
    }
}

// ---------------- launch ----------------
extern "C" void kernel_launch(void* const* d_in, const int* in_sizes, int n_in,
                              void* d_out, int out_size) {
    const float* x_in       = (const float*)d_in[0];
    const int*   eidx       = (const int*)  d_in[1];
    const float* edge_attr  = (const float*)d_in[2];
    const float* pos_attr   = (const float*)d_in[4];
    const float* neg_attr   = (const float*)d_in[6];
    const float* avg_dl     = (const float*)d_in[7];
    const float* node_emb_w = (const float*)d_in[8];
    const float* node_emb_b = (const float*)d_in[9];
    const float* edge_emb_w = (const float*)d_in[10];
    const float* edge_emb_b = (const float*)d_in[11];
    const float* eenc_w     = (const float*)d_in[12];
    const float* eenc_b     = (const float*)d_in[13];
    const float* pre_w      = (const float*)d_in[14];
    const float* pre_b      = (const float*)d_in[15];
    const float* post_w     = (const float*)d_in[16];
    const float* post_b     = (const float*)d_in[17];
    const float* lin_w      = (const float*)d_in[18];
    const float* lin_b      = (const float*)d_in[19];
    const float* emlp_w1    = (const float*)d_in[20];
    const float* emlp_b1    = (const float*)d_in[21];
    const float* emlp_w2    = (const float*)d_in[22];
    const float* emlp_b2    = (const float*)d_in[23];
    const float* bn_g       = (const float*)d_in[24];
    const float* bn_b       = (const float*)d_in[25];

    const int* src = eidx;          // edge_index[0]
    const int* dst = eidx + EE;     // edge_index[1]

    float* out     = (float*)d_out;
    float* pos_out = out + (long)NN * HH;
    float* neg_out = pos_out + (long)EPP * HH;

    float *p_x, *p_ea, *p_upd, *p_lin, *p_s1, *p_s2, *p_mn, *p_mx, *p_amp, *p_att, *p_cw, *p_cb, *p_cb2;
    float2* p_wt;
    cudaGetSymbolAddress((void**)&p_x, g_x);
    cudaGetSymbolAddress((void**)&p_ea, g_ea);
    cudaGetSymbolAddress((void**)&p_upd, g_upd);
    cudaGetSymbolAddress((void**)&p_lin, g_lin);
    cudaGetSymbolAddress((void**)&p_s1, g_s1);
    cudaGetSymbolAddress((void**)&p_s2, g_s2);
    cudaGetSymbolAddress((void**)&p_mn, g_mn);
    cudaGetSymbolAddress((void**)&p_mx, g_mx);
    cudaGetSymbolAddress((void**)&p_amp, g_amp);
    cudaGetSymbolAddress((void**)&p_att, g_att);
    cudaGetSymbolAddress((void**)&p_cw, g_cw);
    cudaGetSymbolAddress((void**)&p_cb, g_cb);
    cudaGetSymbolAddress((void**)&p_cb2, g_cb2);
    cudaGetSymbolAddress((void**)&p_wt, g_wt);

    const int NB_N  = (NN + 127) / 128;      // 391
    const int NB_E  = (EE + 127) / 128;      // 3125
    const int NB_EP = (EPP + 127) / 128;     // 313
    const int TPB = 256;
    const int GB_N = (NN + TPB - 1) / TPB;
    const int GB_E = (EE + TPB - 1) / TPB;
    const long NH = (long)NN * HH;
    const int GB_NH = (int)((NH + TPB - 1) / TPB);

    auto prepW = [&](const float* w, int K) {
        int nf2 = (K / 16) * 1024;
        k_prep_w<<<(nf2 + 255) / 256, 256>>>(w, p_wt, nf2);
    };

    // degree + amp/att (static over layers)
    k_zero_deg<<<GB_N, TPB>>>();
    k_count_deg<<<GB_E, TPB>>>(dst);
    k_amp_att<<<GB_N, TPB>>>(avg_dl);

    // embeddings
    prepW(node_emb_w, FF);
    gemm_mma<<<NB_N, 256>>>(PlainLd{x_in, FF}, StoreEp{p_x}, p_wt, node_emb_b, NN, FF);
    prepW(edge_emb_w, EDD);
    gemm_mma<<<NB_E, 256>>>(PlainLd{edge_attr, EDD}, StoreEp{p_ea}, p_wt, edge_emb_b, EE, EDD);
    gemm_mma<<<NB_EP, 256>>>(PlainLd{pos_attr, EDD}, StoreEp{pos_out}, p_wt, edge_emb_b, EPP, EDD);
    gemm_mma<<<NB_EP, 256>>>(PlainLd{neg_attr, EDD}, StoreEp{neg_out}, p_wt, edge_emb_b, EPP, EDD);

    for (int l = 0; l < LL; l++) {
        const float* eW  = eenc_w  + (long)l * HH * HH;
        const float* eB  = eenc_b  + (long)l * HH;
        const float* pW  = pre_w   + (long)l * 3 * HH * HH;
        const float* pB  = pre_b   + (long)l * HH;
        const float* poW = post_w  + (long)l * 13 * HH * HH;
        const float* poB = post_b  + (long)l * HH;
        const float* lW  = lin_w   + (long)l * HH * HH;
        const float* lB  = lin_b   + (long)l * HH;
        const float* m1W = emlp_w1 + (long)l * 3 * HH * HH;
        const float* m1B = emlp_b1 + (long)l * HH;
        const float* m2W = emlp_w2 + (long)l * HH * HH;
        const float* m2B = emlp_b2 + (long)l * HH;
        const float* bG  = bn_g    + (long)l * HH;
        const float* bB  = bn_b    + (long)l * HH;

        k_init_agg<<<GB_NH, TPB>>>();
        k_zero_bn<<<1, HH>>>();

        // composite pre weight: [pW1; pW2; eW@pW3], bias pB + eB@pW3
        k_comp_pre<<<384, 128>>>(eW, pW, p_cw);
        k_comp_pre_b<<<1, 128>>>(eB, pW, pB, p_cb);
        prepW(p_cw, 3 * HH);
        // h = [x[dst], x[src], ea] @ W' + b'   (fused segment agg epilogue)
        gemm_mma<<<NB_E, 256>>>(GatherLd{p_x, dst, src, p_ea},
                                AggEp{p_s1, p_s2, p_mn, p_mx, dst}, p_wt, p_cb, EE, 3 * HH);

        k_fin_agg<<<GB_NH, TPB>>>();

        // composite post+lin weight: poW@lW, bias poB@lW + lB
        k_comp_post<<<13 * HH, 128>>>(poW, lW, p_cw);
        k_comp_post_b<<<1, 128>>>(poB, lW, lB, p_cb2);
        prepW(p_cw, 13 * HH);
        // out = [x, agg, agg*amp, agg*att] @ (poW@lW) + b''
        gemm_mma<<<NB_N, 256>>>(PostLd{p_x, p_s1, p_mn, p_mx, p_s2, p_amp, p_att},
                                StoreEp{p_lin}, p_wt, p_cb2, NN, 13 * HH);

        k_bn_stats<<<256, HH>>>(p_lin);
        k_bn_fin<<<1, HH>>>();
        k_apply<<<GB_NH, TPB>>>(bG, bB, (l == LL - 1) ? out : (float*)nullptr);

        // upd = relu([x[src], x[dst], ea] @ emlp_w1 + b1)
        prepW(m1W, 3 * HH);
        gemm_mma<<<NB_E, 256>>>(GatherLd{p_x, src, dst, p_ea},
                                ReluEp{p_upd}, p_wt, m1B, EE, 3 * HH);
        // ea = ea + (upd @ emlp_w2 + b2) / 2
        prepW(m2W, HH);
        gemm_mma<<<NB_E, 256>>>(PlainLd{p_upd, HH}, EaEp{p_ea}, p_wt, m2B, EE, HH);
    }
}

// round 9
// speedup vs baseline: 1.4334x; 1.4334x over previous
#include <cuda_runtime.h>
#include <cstdint>
#include <math.h>

#define NN 50000
#define EE 400000
#define EPP 40000
#define FF 64
#define EDD 32
#define HH 128
#define LL 2

// ---------------- scratch (device globals; no allocation allowed) ----------------
__device__ float g_x[NN * HH];
__device__ float g_ea[EE * HH];
__device__ float g_upd[EE * HH];
__device__ float g_lin[NN * HH];
__device__ float g_s1[NN * HH];   // becomes mean after finalize
__device__ float g_s2[NN * HH];   // becomes std after finalize
__device__ float g_mn[NN * HH];
__device__ float g_mx[NN * HH];
__device__ float g_cw[1664 * 128];      // composite fp32 weights
__device__ float g_cb[HH];              // composite bias (pre)
__device__ float g_cb2[HH];             // composite bias (post)
__device__ float g_zb[HH];              // zero bias
__device__ float2 g_wt[(1664 / 16) * 1024];   // fragment-ordered tf32 weights
__device__ float2 g_wt2[(128 / 16) * 1024];   // small second fragment buffer
__device__ int   g_deg[NN];
__device__ float g_amp[NN];
__device__ float g_att[NN];
__device__ float g_bnsum[HH];
__device__ float g_bnsq[HH];
__device__ float g_bnmu[HH];
__device__ float g_bnrstd[HH];

// ---------------- helpers ----------------
__device__ __forceinline__ uint32_t smem_u32(const void* p) {
    uint32_t a;
    asm("{ .reg .u64 t; cvta.to.shared.u64 t, %1; cvt.u32.u64 %0, t; }" : "=r"(a) : "l"(p));
    return a;
}
__device__ __forceinline__ uint32_t f2tf32(float x) {
    uint32_t r; asm("cvt.rn.tf32.f32 %0, %1;" : "=r"(r) : "f"(x)); return r;
}
__device__ __forceinline__ void cp16(uint32_t sdst, const void* gsrc, bool full) {
    int sz = full ? 16 : 0;
    asm volatile("cp.async.cg.shared.global [%0], [%1], 16, %2;"
                 :: "r"(sdst), "l"(gsrc), "r"(sz) : "memory");
}
__device__ __forceinline__ void cp_commit() {
    asm volatile("cp.async.commit_group;" ::: "memory");
}
__device__ __forceinline__ void mma_tf32(float c[4], const uint32_t a[4], const uint32_t b[2]) {
    asm volatile(
        "mma.sync.aligned.m16n8k8.row.col.f32.tf32.tf32.f32 "
        "{%0,%1,%2,%3}, {%4,%5,%6,%7}, {%8,%9}, {%0,%1,%2,%3};\n"
        : "+f"(c[0]), "+f"(c[1]), "+f"(c[2]), "+f"(c[3])
        : "r"(a[0]), "r"(a[1]), "r"(a[2]), "r"(a[3]), "r"(b[0]), "r"(b[1]));
}

// ---------------- atomic float min/max ----------------
__device__ __forceinline__ void atomicMaxF(float* a, float v) {
    if (v >= 0.f) atomicMax((int*)a, __float_as_int(v));
    else          atomicMin((unsigned int*)a, __float_as_uint(v));
}
__device__ __forceinline__ void atomicMinF(float* a, float v) {
    if (v >= 0.f) atomicMin((int*)a, __float_as_int(v));
    else          atomicMax((unsigned int*)a, __float_as_uint(v));
}

// ---------------- A-tile loaders: ptr4(r,k) -> gmem pointer to 4 floats ----------------
struct PlainLd {
    const float* __restrict__ A; int K;
    static constexpr bool scaled = false;
    __device__ __forceinline__ const float* ptr4(int r, int k) const {
        return A + (long)r * K + k;
    }
    __device__ __forceinline__ float rowscale(int, int) const { return 1.f; }
};
struct GatherLd {  // [x[i0[r]], x[i1[r]], third[r]]  (each 128 wide)
    const float* __restrict__ x;
    const int* __restrict__ i0;
    const int* __restrict__ i1;
    const float* __restrict__ third;
    static constexpr bool scaled = false;
    __device__ __forceinline__ const float* ptr4(int r, int k) const {
        if (k < 128) return x + (long)i0[r] * 128 + k;
        if (k < 256) return x + (long)i1[r] * 128 + (k - 128);
        return third + (long)r * 128 + (k - 256);
    }
    __device__ __forceinline__ float rowscale(int, int) const { return 1.f; }
};
struct PostLd {  // [x, agg, agg*amp, agg*att]; agg = [mean, mn, mx, std]
    const float* __restrict__ x;
    const float* __restrict__ mean;
    const float* __restrict__ mn;
    const float* __restrict__ mx;
    const float* __restrict__ sd;
    const float* __restrict__ amp;
    const float* __restrict__ att;
    static constexpr bool scaled = true;
    __device__ __forceinline__ const float* ptr4(int r, int k) const {
        if (k < 128) return x + (long)r * 128 + k;
        int rem = (k - 128) & 511;
        int a   = rem >> 7;       // 0 mean, 1 mn, 2 mx, 3 std
        int c   = rem & 127;
        const float* base = (a == 0) ? mean : (a == 1) ? mn : (a == 2) ? mx : sd;
        return base + (long)r * 128 + c;
    }
    __device__ __forceinline__ float rowscale(int r, int k) const {
        if (k < 128) return 1.f;
        int grp = (k - 128) >> 9;   // 0: raw, 1: *amp, 2: *att
        return (grp == 1) ? amp[r] : (grp == 2) ? att[r] : 1.f;
    }
};

// ---------------- epilogues ----------------
struct StoreEp {
    float* __restrict__ o;
    __device__ __forceinline__ void pair(int r, int c, float v0, float v1) const {
        *(float2*)(o + (long)r * 128 + c) = make_float2(v0, v1);
    }
};
struct ReluEp {
    float* __restrict__ o;
    __device__ __forceinline__ void pair(int r, int c, float v0, float v1) const {
        *(float2*)(o + (long)r * 128 + c) = make_float2(fmaxf(v0, 0.f), fmaxf(v1, 0.f));
    }
};
struct EaEp {  // ea += v/2
    float* __restrict__ ea;
    __device__ __forceinline__ void pair(int r, int c, float v0, float v1) const {
        float2* p = (float2*)(ea + (long)r * 128 + c);
        float2 cur = *p;
        cur.x += 0.5f * v0; cur.y += 0.5f * v1;
        *p = cur;
    }
};
struct AggEp {  // segment sum / sumsq / min / max over dst
    float* __restrict__ s1; float* __restrict__ s2;
    float* __restrict__ mn; float* __restrict__ mx;
    const int* __restrict__ dst;
    __device__ __forceinline__ void one(long o, float v) const {
        atomicAdd(s1 + o, v);
        atomicAdd(s2 + o, v * v);
        atomicMaxF(mx + o, v);
        atomicMinF(mn + o, v);
    }
    __device__ __forceinline__ void pair(int r, int c, float v0, float v1) const {
        long o = (long)dst[r] * 128 + c;
        one(o, v0);
        one(o + 1, v1);
    }
};

// ---------------- weight prep: fragment-ordered tf32 ----------------
// Wp float2 index ((c*2 + s)*128 + n)*4 + t  <-  {W[16c+8s+t][n], W[16c+8s+t+4][n]}
__global__ void k_prep_w(const float* __restrict__ W, float2* __restrict__ Wp, int nf2) {
    int i = blockIdx.x * blockDim.x + threadIdx.x;
    if (i < nf2) {
        int t = i & 3, n = (i >> 2) & 127, s = (i >> 9) & 1, c = i >> 10;
        int k = c * 16 + s * 8 + t;
        Wp[i] = make_float2(__uint_as_float(f2tf32(W[(long)k * 128 + n])),
                            __uint_as_float(f2tf32(W[(long)(k + 4) * 128 + n])));
    }
}
// two-source variant: k < ksplit from W0, else W1[k - ksplit]
__global__ void k_prep_w2(const float* __restrict__ W0, const float* __restrict__ W1,
                          int ksplit, float2* __restrict__ Wp, int nf2) {
    int i = blockIdx.x * blockDim.x + threadIdx.x;
    if (i < nf2) {
        int t = i & 3, n = (i >> 2) & 127, s = (i >> 9) & 1, c = i >> 10;
        int k = c * 16 + s * 8 + t;
        int k2 = k + 4;
        float a = (k  < ksplit) ? W0[(long)k  * 128 + n] : W1[(long)(k  - ksplit) * 128 + n];
        float b = (k2 < ksplit) ? W0[(long)k2 * 128 + n] : W1[(long)(k2 - ksplit) * 128 + n];
        Wp[i] = make_float2(__uint_as_float(f2tf32(a)), __uint_as_float(f2tf32(b)));
    }
}

// ---------------- composite bias builders (1 block, cheap) ----------------
__global__ void k_comp_pre_b(const float* __restrict__ eB, const float* __restrict__ pW,
                             const float* __restrict__ pB, float* __restrict__ cb) {
    int n = threadIdx.x;
    float s = pB[n];
    for (int j = 0; j < 128; j++) s += eB[j] * pW[(long)(256 + j) * 128 + n];
    cb[n] = s;
}
__global__ void k_comp_post_b(const float* __restrict__ poB, const float* __restrict__ lW,
                              const float* __restrict__ lB, float* __restrict__ cb) {
    int n = threadIdx.x;
    float s = lB[n];
    for (int j = 0; j < 128; j++) s += poB[j] * lW[(long)j * 128 + n];
    cb[n] = s;
}
__global__ void k_zero_zb() { g_zb[threadIdx.x] = 0.f; }

// ---------------- tensor-core GEMM: out[M,128] = A[M,K] @ W[K,128] + b ----------------
// 128x128 CTA tile, 256 threads = 8 warps (4 M x 2 N), warp tile 32x64.
// mma.sync m16n8k8 tf32. K chunk = 16, 3-stage cp.async pipeline.
// Weights pre-rounded tf32 in fragment order (k_prep_w / k_prep_w2).
#define KT 16
#define NSTG 3
#define AP 20    // A row pitch (floats)

template <typename Loader, typename Epi>
__global__ void __launch_bounds__(256, 2) gemm_mma(
    Loader ld, Epi ep,
    const float2* __restrict__ Wp, const float* __restrict__ bias,
    int M, int K)
{
    __shared__ float As[NSTG][128 * AP];
    __shared__ float Ws[NSTG][KT * 128];     // fragment-ordered chunk (8KB)
    const int tid  = threadIdx.x;
    const int lane = tid & 31;
    const int wid  = tid >> 5;
    const int wm   = wid & 3;        // warp row: 32 rows each
    const int wn   = wid >> 2;       // warp col: 64 cols each
    const int gid  = lane >> 2;      // 0..7
    const int tid4 = lane & 3;       // 0..3
    const int row0 = blockIdx.x * 128;

    const int sr0 = tid >> 2,  sq0 = tid & 3;
    const int sr1 = sr0 + 64;

    const uint32_t sA = smem_u32(&As[0][0]);
    const uint32_t sW = smem_u32(&Ws[0][0]);

    float acc[2][8][4];
#pragma unroll
    for (int mt = 0; mt < 2; mt++)
#pragma unroll
        for (int nt = 0; nt < 8; nt++)
#pragma unroll
            for (int i = 0; i < 4; i++) acc[mt][nt][i] = 0.f;

    const int nch = K / KT;

    auto stage = [&](int buf, int ch) {
        int k0 = ch * KT;
        uint32_t a_base = sA + buf * (128 * AP * 4);
        uint32_t w_base = sW + buf * (KT * 128 * 4);
        int g0 = row0 + sr0, g1 = row0 + sr1;
        bool v0 = g0 < M, v1 = g1 < M;
        cp16(a_base + (sr0 * AP + sq0 * 4) * 4, ld.ptr4(v0 ? g0 : 0, k0 + sq0 * 4), v0);
        cp16(a_base + (sr1 * AP + sq0 * 4) * 4, ld.ptr4(v1 ? g1 : 0, k0 + sq0 * 4), v1);
        const char* wsrc = (const char*)Wp + (long)ch * 8192;
        cp16(w_base + tid * 16,         wsrc + tid * 16,         true);
        cp16(w_base + (tid + 256) * 16, wsrc + (tid + 256) * 16, true);
        cp_commit();
    };

    int ncommit = 0;
    stage(0, 0); ncommit++;
    if (nch > 1) { stage(1, 1); ncommit++; }

    for (int ch = 0; ch < nch; ch++) {
        const int buf = ch % NSTG;
        const int k0 = ch * KT;
        if (ch + 2 < nch) { stage((ch + 2) % NSTG, ch + 2); ncommit++; }
        int allow = ncommit - ch - 1;
        if (allow >= 2)      asm volatile("cp.async.wait_group 2;" ::: "memory");
        else if (allow == 1) asm volatile("cp.async.wait_group 1;" ::: "memory");
        else                 asm volatile("cp.async.wait_group 0;" ::: "memory");
        __syncthreads();

        // per-chunk row scales (PostLd only)
        float rs[2][2];
        if constexpr (Loader::scaled) {
#pragma unroll
            for (int mt = 0; mt < 2; mt++) {
                int m0 = row0 + wm * 32 + mt * 16;
                int rA = m0 + gid, rB = m0 + 8 + gid;
                rs[mt][0] = ld.rowscale(rA < M ? rA : 0, k0);
                rs[mt][1] = ld.rowscale(rB < M ? rB : 0, k0);
            }
        }

        const float* Ab = &As[buf][0];
        const float2* Bb = (const float2*)&Ws[buf][0];
#pragma unroll
        for (int ks = 0; ks < KT; ks += 8) {
            const int s = ks >> 3;
            uint32_t a[2][4];
#pragma unroll
            for (int mt = 0; mt < 2; mt++) {
                int m0 = wm * 32 + mt * 16;
                float a0 = Ab[(m0 + gid) * AP + ks + tid4];
                float a1 = Ab[(m0 + 8 + gid) * AP + ks + tid4];
                float a2 = Ab[(m0 + gid) * AP + ks + tid4 + 4];
                float a3 = Ab[(m0 + 8 + gid) * AP + ks + tid4 + 4];
                if constexpr (Loader::scaled) {
                    a0 *= rs[mt][0]; a1 *= rs[mt][1];
                    a2 *= rs[mt][0]; a3 *= rs[mt][1];
                }
                a[mt][0] = f2tf32(a0); a[mt][1] = f2tf32(a1);
                a[mt][2] = f2tf32(a2); a[mt][3] = f2tf32(a3);
            }
            uint32_t b[8][2];
#pragma unroll
            for (int nt = 0; nt < 8; nt++) {
                int n = wn * 64 + nt * 8 + gid;
                float2 v = Bb[s * 512 + n * 4 + tid4];
                b[nt][0] = __float_as_uint(v.x);
                b[nt][1] = __float_as_uint(v.y);
            }
#pragma unroll
            for (int mt = 0; mt < 2; mt++)
#pragma unroll
                for (int nt = 0; nt < 8; nt++)
                    mma_tf32(acc[mt][nt], a[mt], b[nt]);
        }
        __syncthreads();
    }

    // epilogue
    float bv[8][2];
#pragma unroll
    for (int nt = 0; nt < 8; nt++) {
        int c = wn * 64 + nt * 8 + 2 * tid4;
        bv[nt][0] = bias[c];
        bv[nt][1] = bias[c + 1];
    }
#pragma unroll
    for (int mt = 0; mt < 2; mt++) {
        int rA = row0 + wm * 32 + mt * 16 + gid;
        int rB = rA + 8;
#pragma unroll
        for (int nt = 0; nt < 8; nt++) {
            int c = wn * 64 + nt * 8 + 2 * tid4;
            if (rA < M) ep.pair(rA, c, acc[mt][nt][0] + bv[nt][0], acc[mt][nt][1] + bv[nt][1]);
            if (rB < M) ep.pair(rB, c, acc[mt][nt][2] + bv[nt][0], acc[mt][nt][3] + bv[nt][1]);
        }
    }
}

// ---------------- small kernels ----------------
__global__ void k_zero_deg() {
    int i = blockIdx.x * blockDim.x + threadIdx.x;
    if (i < NN) g_deg[i] = 0;
}
__global__ void k_count_deg(const int* __restrict__ dst) {
    int e = blockIdx.x * blockDim.x + threadIdx.x;
    if (e < EE) atomicAdd(&g_deg[dst[e]], 1);
}
__global__ void k_amp_att(const float* __restrict__ adl) {
    int i = blockIdx.x * blockDim.x + threadIdx.x;
    if (i < NN) {
        float d = fmaxf((float)g_deg[i], 1.f);
        float lg = logf(d + 1.f);
        float a = adl[0];
        g_amp[i] = lg / a;
        g_att[i] = a / lg;
    }
}
__global__ void k_init_agg() {   // float4-vectorized init of 4 agg arrays
    long i = (long)blockIdx.x * blockDim.x + threadIdx.x;   // float4 index
    if (i < (long)NN * HH / 4) {
        const float4 z = make_float4(0.f, 0.f, 0.f, 0.f);
        float pinf = __int_as_float(0x7f800000);
        float ninf = __int_as_float(0xff800000);
        ((float4*)g_s1)[i] = z;
        ((float4*)g_s2)[i] = z;
        ((float4*)g_mn)[i] = make_float4(pinf, pinf, pinf, pinf);
        ((float4*)g_mx)[i] = make_float4(ninf, ninf, ninf, ninf);
    }
}
__global__ void k_zero_bn() {
    int c = threadIdx.x;
    g_bnsum[c] = 0.f;
    g_bnsq[c] = 0.f;
}
__global__ void k_fin_agg() {
    long i = (long)blockIdx.x * blockDim.x + threadIdx.x;
    if (i < (long)NN * HH) {
        int n = (int)(i >> 7);
        int d = g_deg[n];
        float degc = fmaxf((float)d, 1.f);
        float m = g_s1[i] / degc;
        float var = g_s2[i] / degc - m * m;
        g_s1[i] = m;
        g_s2[i] = sqrtf(fmaxf(var, 0.f) + 1e-5f);
        if (d == 0) { g_mn[i] = 0.f; g_mx[i] = 0.f; }
    }
}
__global__ void k_bn_stats(const float* __restrict__ o) {
    int c = threadIdx.x;           // 128 threads
    float s = 0.f, s2 = 0.f;
    for (int r = blockIdx.x; r < NN; r += gridDim.x) {
        float v = o[(long)r * 128 + c];
        s += v; s2 += v * v;
    }
    atomicAdd(&g_bnsum[c], s);
    atomicAdd(&g_bnsq[c], s2);
}
__global__ void k_bn_fin() {
    int c = threadIdx.x;
    float mu = g_bnsum[c] / (float)NN;
    float var = g_bnsq[c] / (float)NN - mu * mu;
    g_bnmu[c] = mu;
    g_bnrstd[c] = rsqrtf(var + 1e-5f);
}
__global__ void k_apply(const float* __restrict__ bng, const float* __restrict__ bnb,
                        float* __restrict__ xout) {
    long i = (long)blockIdx.x * blockDim.x + threadIdx.x;
    if (i < (long)NN * HH) {
        int c = (int)(i & 127);
        float v = bng[c] * (g_lin[i] - g_bnmu[c]) * g_bnrstd[c] + bnb[c];
        float nx = (g_x[i] + fmaxf(v, 0.f)) * 0.5f;
        g_x[i] = nx;
        if (xout) xout[i] = nx;
    }
}

// ---------------- launch ----------------
extern "C" void kernel_launch(void* const* d_in, const int* in_sizes, int n_in,
                              void* d_out, int out_size) {
    const float* x_in       = (const float*)d_in[0];
    const int*   eidx       = (const int*)  d_in[1];
    const float* edge_attr  = (const float*)d_in[2];
    const float* pos_attr   = (const float*)d_in[4];
    const float* neg_attr   = (const float*)d_in[6];
    const float* avg_dl     = (const float*)d_in[7];
    const float* node_emb_w = (const float*)d_in[8];
    const float* node_emb_b = (const float*)d_in[9];
    const float* edge_emb_w = (const float*)d_in[10];
    const float* edge_emb_b = (const float*)d_in[11];
    const float* eenc_w     = (const float*)d_in[12];
    const float* eenc_b     = (const float*)d_in[13];
    const float* pre_w      = (const float*)d_in[14];
    const float* pre_b      = (const float*)d_in[15];
    const float* post_w     = (const float*)d_in[16];
    const float* post_b     = (const float*)d_in[17];
    const float* lin_w      = (const float*)d_in[18];
    const float* lin_b      = (const float*)d_in[19];
    const float* emlp_w1    = (const float*)d_in[20];
    const float* emlp_b1    = (const float*)d_in[21];
    const float* emlp_w2    = (const float*)d_in[22];
    const float* emlp_b2    = (const float*)d_in[23];
    const float* bn_g       = (const float*)d_in[24];
    const float* bn_b       = (const float*)d_in[25];

    const int* src = eidx;          // edge_index[0]
    const int* dst = eidx + EE;     // edge_index[1]

    float* out     = (float*)d_out;
    float* pos_out = out + (long)NN * HH;
    float* neg_out = pos_out + (long)EPP * HH;

    float *p_x, *p_ea, *p_upd, *p_lin, *p_s1, *p_s2, *p_mn, *p_mx, *p_amp, *p_att;
    float *p_cw, *p_cb, *p_cb2, *p_zb;
    float2 *p_wt, *p_wt2;
    cudaGetSymbolAddress((void**)&p_x, g_x);
    cudaGetSymbolAddress((void**)&p_ea, g_ea);
    cudaGetSymbolAddress((void**)&p_upd, g_upd);
    cudaGetSymbolAddress((void**)&p_lin, g_lin);
    cudaGetSymbolAddress((void**)&p_s1, g_s1);
    cudaGetSymbolAddress((void**)&p_s2, g_s2);
    cudaGetSymbolAddress((void**)&p_mn, g_mn);
    cudaGetSymbolAddress((void**)&p_mx, g_mx);
    cudaGetSymbolAddress((void**)&p_amp, g_amp);
    cudaGetSymbolAddress((void**)&p_att, g_att);
    cudaGetSymbolAddress((void**)&p_cw, g_cw);
    cudaGetSymbolAddress((void**)&p_cb, g_cb);
    cudaGetSymbolAddress((void**)&p_cb2, g_cb2);
    cudaGetSymbolAddress((void**)&p_zb, g_zb);
    cudaGetSymbolAddress((void**)&p_wt, g_wt);
    cudaGetSymbolAddress((void**)&p_wt2, g_wt2);

    const int NB_N  = (NN + 127) / 128;      // 391
    const int NB_E  = (EE + 127) / 128;      // 3125
    const int NB_EP = (EPP + 127) / 128;     // 313
    const int TPB = 256;
    const int GB_N = (NN + TPB - 1) / TPB;
    const int GB_E = (EE + TPB - 1) / TPB;
    const long NH = (long)NN * HH;
    const int GB_NH = (int)((NH + TPB - 1) / TPB);

    auto prepW = [&](const float* w, int K, float2* dstp) {
        int nf2 = (K / 16) * 1024;
        k_prep_w<<<(nf2 + 255) / 256, 256>>>(w, dstp, nf2);
    };

    // one-time
    k_zero_zb<<<1, HH>>>();
    k_zero_deg<<<GB_N, TPB>>>();
    k_count_deg<<<GB_E, TPB>>>(dst);
    k_amp_att<<<GB_N, TPB>>>(avg_dl);

    // embeddings
    prepW(node_emb_w, FF, p_wt);
    gemm_mma<<<NB_N, 256>>>(PlainLd{x_in, FF}, StoreEp{p_x}, p_wt, node_emb_b, NN, FF);
    prepW(edge_emb_w, EDD, p_wt);
    gemm_mma<<<NB_E, 256>>>(PlainLd{edge_attr, EDD}, StoreEp{p_ea}, p_wt, edge_emb_b, EE, EDD);
    gemm_mma<<<NB_EP, 256>>>(PlainLd{pos_attr, EDD}, StoreEp{pos_out}, p_wt, edge_emb_b, EPP, EDD);
    gemm_mma<<<NB_EP, 256>>>(PlainLd{neg_attr, EDD}, StoreEp{neg_out}, p_wt, edge_emb_b, EPP, EDD);

    for (int l = 0; l < LL; l++) {
        const float* eW  = eenc_w  + (long)l * HH * HH;
        const float* eB  = eenc_b  + (long)l * HH;
        const float* pW  = pre_w   + (long)l * 3 * HH * HH;
        const float* pB  = pre_b   + (long)l * HH;
        const float* poW = post_w  + (long)l * 13 * HH * HH;
        const float* poB = post_b  + (long)l * HH;
        const float* lW  = lin_w   + (long)l * HH * HH;
        const float* lB  = lin_b   + (long)l * HH;
        const float* m1W = emlp_w1 + (long)l * 3 * HH * HH;
        const float* m1B = emlp_b1 + (long)l * HH;
        const float* m2W = emlp_w2 + (long)l * HH * HH;
        const float* m2B = emlp_b2 + (long)l * HH;
        const float* bG  = bn_g    + (long)l * HH;
        const float* bB  = bn_b    + (long)l * HH;

        k_init_agg<<<GB_NH / 4 + 1, TPB>>>();
        k_zero_bn<<<1, HH>>>();

        // --- composite pre weight via tensor GEMM: cw_tail = eW @ pW3 ---
        const float* pW3 = pW + 256 * 128;
        prepW(pW3, HH, p_wt2);
        gemm_mma<<<1, 256>>>(PlainLd{eW, HH}, StoreEp{p_cw}, p_wt2, p_zb, 128, HH);
        k_comp_pre_b<<<1, 128>>>(eB, pW, pB, p_cb);
        {   // fragment-order: [pW rows 0..255 ; cw rows 0..127]
            int nf2 = (3 * HH / 16) * 1024;
            k_prep_w2<<<(nf2 + 255) / 256, 256>>>(pW, p_cw, 256, p_wt, nf2);
        }
        // h = [x[dst], x[src], ea] @ W' + b'   (fused segment agg epilogue)
        gemm_mma<<<NB_E, 256>>>(GatherLd{p_x, dst, src, p_ea},
                                AggEp{p_s1, p_s2, p_mn, p_mx, dst}, p_wt, p_cb, EE, 3 * HH);

        k_fin_agg<<<GB_NH, TPB>>>();

        // --- composite post+lin weight via tensor GEMM: cw = poW @ lW ---
        prepW(lW, HH, p_wt2);
        gemm_mma<<<13, 256>>>(PlainLd{poW, HH}, StoreEp{p_cw}, p_wt2, p_zb, 13 * HH, HH);
        k_comp_post_b<<<1, 128>>>(poB, lW, lB, p_cb2);
        prepW(p_cw, 13 * HH, p_wt);
        // out = [x, agg, agg*amp, agg*att] @ (poW@lW) + b''
        gemm_mma<<<NB_N, 256>>>(PostLd{p_x, p_s1, p_mn, p_mx, p_s2, p_amp, p_att},
                                StoreEp{p_lin}, p_wt, p_cb2, NN, 13 * HH);

        k_bn_stats<<<256, HH>>>(p_lin);
        k_bn_fin<<<1, HH>>>();
        k_apply<<<GB_NH, TPB>>>(bG, bB, (l == LL - 1) ? out : (float*)nullptr);

        // upd = relu([x[src], x[dst], ea] @ emlp_w1 + b1)
        prepW(m1W, 3 * HH, p_wt);
        gemm_mma<<<NB_E, 256>>>(GatherLd{p_x, src, dst, p_ea},
                                ReluEp{p_upd}, p_wt, m1B, EE, 3 * HH);
        // ea = ea + (upd @ emlp_w2 + b2) / 2
        prepW(m2W, HH, p_wt);
        gemm_mma<<<NB_E, 256>>>(PlainLd{p_upd, HH}, EaEp{p_ea}, p_wt, m2B, EE, HH);
    }
}

// round 11
// speedup vs baseline: 1.7048x; 1.1894x over previous
#include <cuda_runtime.h>
#include <cstdint>
#include <math.h>

#define NN 50000
#define EE 400000
#define EPP 40000
#define FF 64
#define EDD 32
#define HH 128
#define LL 2

// ---------------- scratch (device globals; no allocation allowed) ----------------
__device__ float g_x[NN * HH];
__device__ float g_ea[EE * HH];
__device__ float g_upd[EE * HH];       // doubles as sorted-h buffer during aggregation
__device__ float g_lin[NN * HH];
__device__ float g_s1[NN * HH];        // mean
__device__ float g_s2[NN * HH];        // std
__device__ float g_mn[NN * HH];
__device__ float g_mx[NN * HH];
__device__ float g_cw[1664 * 128];     // composite fp32 weights
__device__ float g_cb[HH];             // composite bias (pre)
__device__ float g_cb2[HH];            // composite bias (post)
__device__ float g_zb[HH];             // zero bias
__device__ float2 g_wt[(1664 / 16) * 1024];   // fragment-ordered tf32 weights
__device__ float2 g_wt2[(128 / 16) * 1024];   // small second fragment buffer
__device__ int   g_deg[NN];
__device__ int   g_rowptr[NN + 1];
__device__ int   g_cur[NN];
__device__ int   g_perm[EE];
__device__ int   g_srcs[EE];
__device__ int   g_dsts[EE];
__device__ float g_amp[NN];
__device__ float g_att[NN];
__device__ float g_bnsum[HH];
__device__ float g_bnsq[HH];
__device__ float g_bnmu[HH];
__device__ float g_bnrstd[HH];

// ---------------- helpers ----------------
__device__ __forceinline__ uint32_t smem_u32(const void* p) {
    uint32_t a;
    asm("{ .reg .u64 t; cvta.to.shared.u64 t, %1; cvt.u32.u64 %0, t; }" : "=r"(a) : "l"(p));
    return a;
}
__device__ __forceinline__ uint32_t f2tf32(float x) {
    uint32_t r; asm("cvt.rn.tf32.f32 %0, %1;" : "=r"(r) : "f"(x)); return r;
}
__device__ __forceinline__ void cp16(uint32_t sdst, const void* gsrc, bool full) {
    int sz = full ? 16 : 0;
    asm volatile("cp.async.cg.shared.global [%0], [%1], 16, %2;"
                 :: "r"(sdst), "l"(gsrc), "r"(sz) : "memory");
}
__device__ __forceinline__ void cp_commit() {
    asm volatile("cp.async.commit_group;" ::: "memory");
}
__device__ __forceinline__ void mma_tf32(float c[4], const uint32_t a[4], const uint32_t b[2]) {
    asm volatile(
        "mma.sync.aligned.m16n8k8.row.col.f32.tf32.tf32.f32 "
        "{%0,%1,%2,%3}, {%4,%5,%6,%7}, {%8,%9}, {%0,%1,%2,%3};\n"
        : "+f"(c[0]), "+f"(c[1]), "+f"(c[2]), "+f"(c[3])
        : "r"(a[0]), "r"(a[1]), "r"(a[2]), "r"(a[3]), "r"(b[0]), "r"(b[1]));
}

// ---------------- A-tile loaders: ptr4(r,k) -> gmem pointer to 4 floats ----------------
struct PlainLd {
    const float* __restrict__ A; int K;
    static constexpr bool scaled = false;
    __device__ __forceinline__ const float* ptr4(int r, int k) const {
        return A + (long)r * K + k;
    }
    __device__ __forceinline__ float rowscale(int, int) const { return 1.f; }
};
struct GatherLd {  // [x[i0[r]], x[i1[r]], third[r]]  (each 128 wide)
    const float* __restrict__ x;
    const int* __restrict__ i0;
    const int* __restrict__ i1;
    const float* __restrict__ third;
    static constexpr bool scaled = false;
    __device__ __forceinline__ const float* ptr4(int r, int k) const {
        if (k < 128) return x + (long)i0[r] * 128 + k;
        if (k < 256) return x + (long)i1[r] * 128 + (k - 128);
        return third + (long)r * 128 + (k - 256);
    }
    __device__ __forceinline__ float rowscale(int, int) const { return 1.f; }
};
struct SortGatherLd {  // rows in dst-sorted edge order: [x[dst_s], x[src_s], ea[perm]]
    const float* __restrict__ x;
    const int* __restrict__ dsts;
    const int* __restrict__ srcs;
    const int* __restrict__ perm;
    const float* __restrict__ ea;
    static constexpr bool scaled = false;
    __device__ __forceinline__ const float* ptr4(int r, int k) const {
        if (k < 128) return x + (long)dsts[r] * 128 + k;
        if (k < 256) return x + (long)srcs[r] * 128 + (k - 128);
        return ea + (long)perm[r] * 128 + (k - 256);
    }
    __device__ __forceinline__ float rowscale(int, int) const { return 1.f; }
};
struct PostLd {  // [x, agg, agg*amp, agg*att]; agg = [mean, mn, mx, std]
    const float* __restrict__ x;
    const float* __restrict__ mean;
    const float* __restrict__ mn;
    const float* __restrict__ mx;
    const float* __restrict__ sd;
    const float* __restrict__ amp;
    const float* __restrict__ att;
    static constexpr bool scaled = true;
    __device__ __forceinline__ const float* ptr4(int r, int k) const {
        if (k < 128) return x + (long)r * 128 + k;
        int rem = (k - 128) & 511;
        int a   = rem >> 7;       // 0 mean, 1 mn, 2 mx, 3 std
        int c   = rem & 127;
        const float* base = (a == 0) ? mean : (a == 1) ? mn : (a == 2) ? mx : sd;
        return base + (long)r * 128 + c;
    }
    __device__ __forceinline__ float rowscale(int r, int k) const {
        if (k < 128) return 1.f;
        int grp = (k - 128) >> 9;   // 0: raw, 1: *amp, 2: *att
        return (grp == 1) ? amp[r] : (grp == 2) ? att[r] : 1.f;
    }
};

// ---------------- epilogues ----------------
struct StoreEp {
    float* __restrict__ o;
    __device__ __forceinline__ void pair(int r, int c, float v0, float v1) const {
        *(float2*)(o + (long)r * 128 + c) = make_float2(v0, v1);
    }
};
struct ReluEp {
    float* __restrict__ o;
    __device__ __forceinline__ void pair(int r, int c, float v0, float v1) const {
        *(float2*)(o + (long)r * 128 + c) = make_float2(fmaxf(v0, 0.f), fmaxf(v1, 0.f));
    }
};
struct EaEp {  // ea += v/2
    float* __restrict__ ea;
    __device__ __forceinline__ void pair(int r, int c, float v0, float v1) const {
        float2* p = (float2*)(ea + (long)r * 128 + c);
        float2 cur = *p;
        cur.x += 0.5f * v0; cur.y += 0.5f * v1;
        *p = cur;
    }
};

// ---------------- weight prep: fragment-ordered tf32 ----------------
__global__ void k_prep_w(const float* __restrict__ W, float2* __restrict__ Wp, int nf2) {
    int i = blockIdx.x * blockDim.x + threadIdx.x;
    if (i < nf2) {
        int t = i & 3, n = (i >> 2) & 127, s = (i >> 9) & 1, c = i >> 10;
        int k = c * 16 + s * 8 + t;
        Wp[i] = make_float2(__uint_as_float(f2tf32(W[(long)k * 128 + n])),
                            __uint_as_float(f2tf32(W[(long)(k + 4) * 128 + n])));
    }
}
__global__ void k_prep_w2(const float* __restrict__ W0, const float* __restrict__ W1,
                          int ksplit, float2* __restrict__ Wp, int nf2) {
    int i = blockIdx.x * blockDim.x + threadIdx.x;
    if (i < nf2) {
        int t = i & 3, n = (i >> 2) & 127, s = (i >> 9) & 1, c = i >> 10;
        int k = c * 16 + s * 8 + t;
        int k2 = k + 4;
        float a = (k  < ksplit) ? W0[(long)k  * 128 + n] : W1[(long)(k  - ksplit) * 128 + n];
        float b = (k2 < ksplit) ? W0[(long)k2 * 128 + n] : W1[(long)(k2 - ksplit) * 128 + n];
        Wp[i] = make_float2(__uint_as_float(f2tf32(a)), __uint_as_float(f2tf32(b)));
    }
}

// ---------------- composite bias builders ----------------
__global__ void k_comp_pre_b(const float* __restrict__ eB, const float* __restrict__ pW,
                             const float* __restrict__ pB, float* __restrict__ cb) {
    int n = threadIdx.x;
    float s = pB[n];
    for (int j = 0; j < 128; j++) s += eB[j] * pW[(long)(256 + j) * 128 + n];
    cb[n] = s;
}
__global__ void k_comp_post_b(const float* __restrict__ poB, const float* __restrict__ lW,
                              const float* __restrict__ lB, float* __restrict__ cb) {
    int n = threadIdx.x;
    float s = lB[n];
    for (int j = 0; j < 128; j++) s += poB[j] * lW[(long)j * 128 + n];
    cb[n] = s;
}
__global__ void k_zero_zb() { g_zb[threadIdx.x] = 0.f; }

// ---------------- tensor-core GEMM: out[M,128] = A[M,K] @ W[K,128] + b ----------------
#define KT 16
#define NSTG 3
#define AP 20    // A row pitch (floats)

template <typename Loader, typename Epi>
__global__ void __launch_bounds__(256, 2) gemm_mma(
    Loader ld, Epi ep,
    const float2* __restrict__ Wp, const float* __restrict__ bias,
    int M, int K)
{
    __shared__ float As[NSTG][128 * AP];
    __shared__ float Ws[NSTG][KT * 128];     // fragment-ordered chunk (8KB)
    const int tid  = threadIdx.x;
    const int lane = tid & 31;
    const int wid  = tid >> 5;
    const int wm   = wid & 3;
    const int wn   = wid >> 2;
    const int gid  = lane >> 2;
    const int tid4 = lane & 3;
    const int row0 = blockIdx.x * 128;

    const int sr0 = tid >> 2,  sq0 = tid & 3;
    const int sr1 = sr0 + 64;

    const uint32_t sA = smem_u32(&As[0][0]);
    const uint32_t sW = smem_u32(&Ws[0][0]);

    float acc[2][8][4];
#pragma unroll
    for (int mt = 0; mt < 2; mt++)
#pragma unroll
        for (int nt = 0; nt < 8; nt++)
#pragma unroll
            for (int i = 0; i < 4; i++) acc[mt][nt][i] = 0.f;

    const int nch = K / KT;

    auto stage = [&](int buf, int ch) {
        int k0 = ch * KT;
        uint32_t a_base = sA + buf * (128 * AP * 4);
        uint32_t w_base = sW + buf * (KT * 128 * 4);
        int g0 = row0 + sr0, g1 = row0 + sr1;
        bool v0 = g0 < M, v1 = g1 < M;
        cp16(a_base + (sr0 * AP + sq0 * 4) * 4, ld.ptr4(v0 ? g0 : 0, k0 + sq0 * 4), v0);
        cp16(a_base + (sr1 * AP + sq0 * 4) * 4, ld.ptr4(v1 ? g1 : 0, k0 + sq0 * 4), v1);
        const char* wsrc = (const char*)Wp + (long)ch * 8192;
        cp16(w_base + tid * 16,         wsrc + tid * 16,         true);
        cp16(w_base + (tid + 256) * 16, wsrc + (tid + 256) * 16, true);
        cp_commit();
    };

    int ncommit = 0;
    stage(0, 0); ncommit++;
    if (nch > 1) { stage(1, 1); ncommit++; }

    for (int ch = 0; ch < nch; ch++) {
        const int buf = ch % NSTG;
        const int k0 = ch * KT;
        if (ch + 2 < nch) { stage((ch + 2) % NSTG, ch + 2); ncommit++; }
        int allow = ncommit - ch - 1;
        if (allow >= 2)      asm volatile("cp.async.wait_group 2;" ::: "memory");
        else if (allow == 1) asm volatile("cp.async.wait_group 1;" ::: "memory");
        else                 asm volatile("cp.async.wait_group 0;" ::: "memory");
        __syncthreads();

        float rs[2][2];
        if constexpr (Loader::scaled) {
#pragma unroll
            for (int mt = 0; mt < 2; mt++) {
                int m0 = row0 + wm * 32 + mt * 16;
                int rA = m0 + gid, rB = m0 + 8 + gid;
                rs[mt][0] = ld.rowscale(rA < M ? rA : 0, k0);
                rs[mt][1] = ld.rowscale(rB < M ? rB : 0, k0);
            }
        }

        const float* Ab = &As[buf][0];
        const float2* Bb = (const float2*)&Ws[buf][0];
#pragma unroll
        for (int ks = 0; ks < KT; ks += 8) {
            const int s = ks >> 3;
            uint32_t a[2][4];
#pragma unroll
            for (int mt = 0; mt < 2; mt++) {
                int m0 = wm * 32 + mt * 16;
                float a0 = Ab[(m0 + gid) * AP + ks + tid4];
                float a1 = Ab[(m0 + 8 + gid) * AP + ks + tid4];
                float a2 = Ab[(m0 + gid) * AP + ks + tid4 + 4];
                float a3 = Ab[(m0 + 8 + gid) * AP + ks + tid4 + 4];
                if constexpr (Loader::scaled) {
                    a0 *= rs[mt][0]; a1 *= rs[mt][1];
                    a2 *= rs[mt][0]; a3 *= rs[mt][1];
                }
                a[mt][0] = f2tf32(a0); a[mt][1] = f2tf32(a1);
                a[mt][2] = f2tf32(a2); a[mt][3] = f2tf32(a3);
            }
            uint32_t b[8][2];
#pragma unroll
            for (int nt = 0; nt < 8; nt++) {
                int n = wn * 64 + nt * 8 + gid;
                float2 v = Bb[s * 512 + n * 4 + tid4];
                b[nt][0] = __float_as_uint(v.x);
                b[nt][1] = __float_as_uint(v.y);
            }
#pragma unroll
            for (int mt = 0; mt < 2; mt++)
#pragma unroll
                for (int nt = 0; nt < 8; nt++)
                    mma_tf32(acc[mt][nt], a[mt], b[nt]);
        }
        __syncthreads();
    }

    float bv[8][2];
#pragma unroll
    for (int nt = 0; nt < 8; nt++) {
        int c = wn * 64 + nt * 8 + 2 * tid4;
        bv[nt][0] = bias[c];
        bv[nt][1] = bias[c + 1];
    }
#pragma unroll
    for (int mt = 0; mt < 2; mt++) {
        int rA = row0 + wm * 32 + mt * 16 + gid;
        int rB = rA + 8;
#pragma unroll
        for (int nt = 0; nt < 8; nt++) {
            int c = wn * 64 + nt * 8 + 2 * tid4;
            if (rA < M) ep.pair(rA, c, acc[mt][nt][0] + bv[nt][0], acc[mt][nt][1] + bv[nt][1]);
            if (rB < M) ep.pair(rB, c, acc[mt][nt][2] + bv[nt][0], acc[mt][nt][3] + bv[nt][1]);
        }
    }
}

// ---------------- CSR build ----------------
__global__ void k_zero_deg() {
    int i = blockIdx.x * blockDim.x + threadIdx.x;
    if (i < NN) g_deg[i] = 0;
}
__global__ void k_count_deg(const int* __restrict__ dst) {
    int e = blockIdx.x * blockDim.x + threadIdx.x;
    if (e < EE) atomicAdd(&g_deg[dst[e]], 1);
}
__global__ void k_prefix() {   // single block, 1024 threads
    __shared__ int sdata[1024];
    __shared__ int s_off;
    int tid = threadIdx.x;
    if (tid == 0) { s_off = 0; g_rowptr[0] = 0; }
    __syncthreads();
    for (int base = 0; base < NN; base += 1024) {
        int i = base + tid;
        int v = (i < NN) ? g_deg[i] : 0;
        sdata[tid] = v;
        __syncthreads();
        for (int d = 1; d < 1024; d <<= 1) {
            int t = (tid >= d) ? sdata[tid - d] : 0;
            __syncthreads();
            sdata[tid] += t;
            __syncthreads();
        }
        if (i < NN) {
            g_rowptr[i + 1] = s_off + sdata[tid];
            g_cur[i] = s_off + sdata[tid] - v;
        }
        __syncthreads();
        if (tid == 0) s_off += sdata[1023];
        __syncthreads();
    }
}
__global__ void k_scatter(const int* __restrict__ src, const int* __restrict__ dst) {
    int e = blockIdx.x * blockDim.x + threadIdx.x;
    if (e < EE) {
        int n = dst[e];
        int pos = atomicAdd(&g_cur[n], 1);
        g_perm[pos] = e;
        g_dsts[pos] = n;
        g_srcs[pos] = src[e];
    }
}
__global__ void k_amp_att(const float* __restrict__ adl) {
    int i = blockIdx.x * blockDim.x + threadIdx.x;
    if (i < NN) {
        float d = fmaxf((float)g_deg[i], 1.f);
        float lg = logf(d + 1.f);
        float a = adl[0];
        g_amp[i] = lg / a;
        g_att[i] = a / lg;
    }
}

// ---------------- segmented reduction: h (sorted) -> mean/std/mn/mx ----------------
__global__ void k_seg_reduce(const float* __restrict__ h) {
    int n = blockIdx.x;
    int c = threadIdx.x;
    int s = g_rowptr[n], e = g_rowptr[n + 1];
    float sum = 0.f, sq = 0.f;
    float mn = __int_as_float(0x7f800000);
    float mx = __int_as_float(0xff800000);
    for (int i = s; i < e; i++) {
        float v = h[(long)i * 128 + c];
        sum += v; sq += v * v;
        mn = fminf(mn, v); mx = fmaxf(mx, v);
    }
    int d = e - s;
    float degc = fmaxf((float)d, 1.f);
    float m = sum / degc;
    float var = sq / degc - m * m;
    long o = (long)n * 128 + c;
    g_s1[o] = m;
    g_s2[o] = sqrtf(fmaxf(var, 0.f) + 1e-5f);
    g_mn[o] = d ? mn : 0.f;
    g_mx[o] = d ? mx : 0.f;
}

// ---------------- BN + residual ----------------
__global__ void k_zero_bn() {
    int c = threadIdx.x;
    g_bnsum[c] = 0.f;
    g_bnsq[c] = 0.f;
}
__global__ void k_bn_stats(const float* __restrict__ o) {
    int c = threadIdx.x;
    float s = 0.f, s2 = 0.f;
    for (int r = blockIdx.x; r < NN; r += gridDim.x) {
        float v = o[(long)r * 128 + c];
        s += v; s2 += v * v;
    }
    atomicAdd(&g_bnsum[c], s);
    atomicAdd(&g_bnsq[c], s2);
}
__global__ void k_bn_fin() {
    int c = threadIdx.x;
    float mu = g_bnsum[c] / (float)NN;
    float var = g_bnsq[c] / (float)NN - mu * mu;
    g_bnmu[c] = mu;
    g_bnrstd[c] = rsqrtf(var + 1e-5f);
}
__global__ void k_apply(const float* __restrict__ bng, const float* __restrict__ bnb,
                        float* __restrict__ xout) {
    long i = (long)blockIdx.x * blockDim.x + threadIdx.x;
    if (i < (long)NN * HH) {
        int c = (int)(i & 127);
        float v = bng[c] * (g_lin[i] - g_bnmu[c]) * g_bnrstd[c] + bnb[c];
        float nx = (g_x[i] + fmaxf(v, 0.f)) * 0.5f;
        g_x[i] = nx;
        if (xout) xout[i] = nx;
    }
}

// ---------------- launch ----------------
extern "C" void kernel_launch(void* const* d_in, const int* in_sizes, int n_in,
                              void* d_out, int out_size) {
    const float* x_in       = (const float*)d_in[0];
    const int*   eidx       = (const int*)  d_in[1];
    const float* edge_attr  = (const float*)d_in[2];
    const float* pos_attr   = (const float*)d_in[4];
    const float* neg_attr   = (const float*)d_in[6];
    const float* avg_dl     = (const float*)d_in[7];
    const float* node_emb_w = (const float*)d_in[8];
    const float* node_emb_b = (const float*)d_in[9];
    const float* edge_emb_w = (const float*)d_in[10];
    const float* edge_emb_b = (const float*)d_in[11];
    const float* eenc_w     = (const float*)d_in[12];
    const float* eenc_b     = (const float*)d_in[13];
    const float* pre_w      = (const float*)d_in[14];
    const float* pre_b      = (const float*)d_in[15];
    const float* post_w     = (const float*)d_in[16];
    const float* post_b     = (const float*)d_in[17];
    const float* lin_w      = (const float*)d_in[18];
    const float* lin_b      = (const float*)d_in[19];
    const float* emlp_w1    = (const float*)d_in[20];
    const float* emlp_b1    = (const float*)d_in[21];
    const float* emlp_w2    = (const float*)d_in[22];
    const float* emlp_b2    = (const float*)d_in[23];
    const float* bn_g       = (const float*)d_in[24];
    const float* bn_b       = (const float*)d_in[25];

    const int* src = eidx;          // edge_index[0]
    const int* dst = eidx + EE;     // edge_index[1]

    float* out     = (float*)d_out;
    float* pos_out = out + (long)NN * HH;
    float* neg_out = pos_out + (long)EPP * HH;

    float *p_x, *p_ea, *p_upd, *p_lin, *p_s1, *p_s2, *p_mn, *p_mx, *p_amp, *p_att;
    float *p_cw, *p_cb, *p_cb2, *p_zb;
    float2 *p_wt, *p_wt2;
    int *p_perm, *p_srcs, *p_dsts;
    cudaGetSymbolAddress((void**)&p_x, g_x);
    cudaGetSymbolAddress((void**)&p_ea, g_ea);
    cudaGetSymbolAddress((void**)&p_upd, g_upd);
    cudaGetSymbolAddress((void**)&p_lin, g_lin);
    cudaGetSymbolAddress((void**)&p_s1, g_s1);
    cudaGetSymbolAddress((void**)&p_s2, g_s2);
    cudaGetSymbolAddress((void**)&p_mn, g_mn);
    cudaGetSymbolAddress((void**)&p_mx, g_mx);
    cudaGetSymbolAddress((void**)&p_amp, g_amp);
    cudaGetSymbolAddress((void**)&p_att, g_att);
    cudaGetSymbolAddress((void**)&p_cw, g_cw);
    cudaGetSymbolAddress((void**)&p_cb, g_cb);
    cudaGetSymbolAddress((void**)&p_cb2, g_cb2);
    cudaGetSymbolAddress((void**)&p_zb, g_zb);
    cudaGetSymbolAddress((void**)&p_wt, g_wt);
    cudaGetSymbolAddress((void**)&p_wt2, g_wt2);
    cudaGetSymbolAddress((void**)&p_perm, g_perm);
    cudaGetSymbolAddress((void**)&p_srcs, g_srcs);
    cudaGetSymbolAddress((void**)&p_dsts, g_dsts);

    const int NB_N  = (NN + 127) / 128;      // 391
    const int NB_E  = (EE + 127) / 128;      // 3125
    const int NB_EP = (EPP + 127) / 128;     // 313
    const int TPB = 256;
    const int GB_N = (NN + TPB - 1) / TPB;
    const int GB_E = (EE + TPB - 1) / TPB;
    const long NH = (long)NN * HH;
    const int GB_NH = (int)((NH + TPB - 1) / TPB);

    auto prepW = [&](const float* w, int K, float2* dstp) {
        int nf2 = (K / 16) * 1024;
        k_prep_w<<<(nf2 + 255) / 256, 256>>>(w, dstp, nf2);
    };

    // one-time: degree, CSR permutation, amp/att
    k_zero_zb<<<1, HH>>>();
    k_zero_deg<<<GB_N, TPB>>>();
    k_count_deg<<<GB_E, TPB>>>(dst);
    k_prefix<<<1, 1024>>>();
    k_scatter<<<GB_E, TPB>>>(src, dst);
    k_amp_att<<<GB_N, TPB>>>(avg_dl);

    // embeddings
    prepW(node_emb_w, FF, p_wt);
    gemm_mma<<<NB_N, 256>>>(PlainLd{x_in, FF}, StoreEp{p_x}, p_wt, node_emb_b, NN, FF);
    prepW(edge_emb_w, EDD, p_wt);
    gemm_mma<<<NB_E, 256>>>(PlainLd{edge_attr, EDD}, StoreEp{p_ea}, p_wt, edge_emb_b, EE, EDD);
    gemm_mma<<<NB_EP, 256>>>(PlainLd{pos_attr, EDD}, StoreEp{pos_out}, p_wt, edge_emb_b, EPP, EDD);
    gemm_mma<<<NB_EP, 256>>>(PlainLd{neg_attr, EDD}, StoreEp{neg_out}, p_wt, edge_emb_b, EPP, EDD);

    for (int l = 0; l < LL; l++) {
        const float* eW  = eenc_w  + (long)l * HH * HH;
        const float* eB  = eenc_b  + (long)l * HH;
        const float* pW  = pre_w   + (long)l * 3 * HH * HH;
        const float* pB  = pre_b   + (long)l * HH;
        const float* poW = post_w  + (long)l * 13 * HH * HH;
        const float* poB = post_b  + (long)l * HH;
        const float* lW  = lin_w   + (long)l * HH * HH;
        const float* lB  = lin_b   + (long)l * HH;
        const float* m1W = emlp_w1 + (long)l * 3 * HH * HH;
        const float* m1B = emlp_b1 + (long)l * HH;
        const float* m2W = emlp_w2 + (long)l * HH * HH;
        const float* m2B = emlp_b2 + (long)l * HH;
        const float* bG  = bn_g    + (long)l * HH;
        const float* bB  = bn_b    + (long)l * HH;

        k_zero_bn<<<1, HH>>>();

        // --- composite pre weight via tensor GEMM: cw_tail = eW @ pW3 ---
        const float* pW3 = pW + 256 * 128;
        prepW(pW3, HH, p_wt2);
        gemm_mma<<<1, 256>>>(PlainLd{eW, HH}, StoreEp{p_cw}, p_wt2, p_zb, 128, HH);
        k_comp_pre_b<<<1, 128>>>(eB, pW, pB, p_cb);
        {
            int nf2 = (3 * HH / 16) * 1024;
            k_prep_w2<<<(nf2 + 255) / 256, 256>>>(pW, p_cw, 256, p_wt, nf2);
        }
        // h(sorted) = [x[dst_s], x[src_s], ea[perm]] @ W' + b'
        gemm_mma<<<NB_E, 256>>>(SortGatherLd{p_x, p_dsts, p_srcs, p_perm, p_ea},
                                StoreEp{p_upd}, p_wt, p_cb, EE, 3 * HH);
        // segmented reduce -> mean/std/mn/mx (finalize fused)
        k_seg_reduce<<<NN, 128>>>(p_upd);

        // --- composite post+lin weight via tensor GEMM: cw = poW @ lW ---
        prepW(lW, HH, p_wt2);
        gemm_mma<<<13, 256>>>(PlainLd{poW, HH}, StoreEp{p_cw}, p_wt2, p_zb, 13 * HH, HH);
        k_comp_post_b<<<1, 128>>>(poB, lW, lB, p_cb2);
        prepW(p_cw, 13 * HH, p_wt);
        // out = [x, agg, agg*amp, agg*att] @ (poW@lW) + b''
        gemm_mma<<<NB_N, 256>>>(PostLd{p_x, p_s1, p_mn, p_mx, p_s2, p_amp, p_att},
                                StoreEp{p_lin}, p_wt, p_cb2, NN, 13 * HH);

        k_bn_stats<<<256, HH>>>(p_lin);
        k_bn_fin<<<1, HH>>>();
        k_apply<<<GB_NH, TPB>>>(bG, bB, (l == LL - 1) ? out : (float*)nullptr);

        // upd = relu([x[src], x[dst], ea] @ emlp_w1 + b1)
        prepW(m1W, 3 * HH, p_wt);
        gemm_mma<<<NB_E, 256>>>(GatherLd{p_x, src, dst, p_ea},
                                ReluEp{p_upd}, p_wt, m1B, EE, 3 * HH);
        // ea = ea + (upd @ emlp_w2 + b2) / 2
        prepW(m2W, HH, p_wt);
        gemm_mma<<<NB_E, 256>>>(PlainLd{p_upd, HH}, EaEp{p_ea}, p_wt, m2B, EE, HH);
    }
}

// round 14
// speedup vs baseline: 2.3578x; 1.3830x over previous
#include <cuda_runtime.h>
#include <cuda_fp16.h>
#include <cstdint>
#include <math.h>

#define NN 50000
#define EE 400000
#define EPP 40000
#define FF 64
#define EDD 32
#define HH 128
#define LL 2

// ---------------- scratch ----------------
__device__ float  g_x[NN * HH];
__device__ __half g_x16[NN * HH];
__device__ float  g_ea[EE * HH];
__device__ __half g_ea16[EE * HH];
__device__ float  g_h[EE * HH];          // sorted pre-output (fp32, for seg stats)
__device__ __half g_upd16[EE * HH];
__device__ float  g_lin[NN * HH];
__device__ __half g_s1h[NN * HH];
__device__ __half g_s2h[NN * HH];
__device__ __half g_mnh[NN * HH];
__device__ __half g_mxh[NN * HH];
__device__ __half g_in16[EE * EDD];      // converted fp32 inputs (reused)
__device__ __half g_xin16[NN * FF];
__device__ __half g_pos16[EPP * EDD];
__device__ __half g_neg16[EPP * EDD];
__device__ __half g_wh16[1664 * 128];    // fp16 copy of fp32 weight (composite A)
__device__ float  g_cw[1664 * 128];      // composite fp32 weights
__device__ float  g_cb[HH];
__device__ float  g_cb2[HH];
__device__ float  g_zb[HH];
__device__ uint32_t g_wt[(1664 / 32) * 2048];   // fragment-ordered fp16 weights
__device__ uint32_t g_wt2[(128 / 32) * 2048];
__device__ int   g_deg[NN];
__device__ int   g_rowptr[NN + 1];
__device__ int   g_cur[NN];
__device__ int   g_bsum[256];
__device__ int   g_bexc[256];
__device__ int   g_perm[EE];
__device__ int   g_srcs[EE];
__device__ int   g_dsts[EE];
__device__ float g_amp[NN];
__device__ float g_att[NN];
__device__ float g_bnsum[HH];
__device__ float g_bnsq[HH];
__device__ float g_bnmu[HH];
__device__ float g_bnrstd[HH];

// ---------------- helpers ----------------
__device__ __forceinline__ uint32_t smem_u32(const void* p) {
    uint32_t a;
    asm("{ .reg .u64 t; cvta.to.shared.u64 t, %1; cvt.u32.u64 %0, t; }" : "=r"(a) : "l"(p));
    return a;
}
__device__ __forceinline__ void cp16(uint32_t sdst, const void* gsrc, bool full) {
    int sz = full ? 16 : 0;
    asm volatile("cp.async.cg.shared.global [%0], [%1], 16, %2;"
                 :: "r"(sdst), "l"(gsrc), "r"(sz) : "memory");
}
__device__ __forceinline__ void cp_commit() {
    asm volatile("cp.async.commit_group;" ::: "memory");
}
__device__ __forceinline__ void mma_f16(float c[4], const uint32_t a[4], const uint32_t b[2]) {
    asm volatile(
        "mma.sync.aligned.m16n8k16.row.col.f32.f16.f16.f32 "
        "{%0,%1,%2,%3}, {%4,%5,%6,%7}, {%8,%9}, {%0,%1,%2,%3};\n"
        : "+f"(c[0]), "+f"(c[1]), "+f"(c[2]), "+f"(c[3])
        : "r"(a[0]), "r"(a[1]), "r"(a[2]), "r"(a[3]), "r"(b[0]), "r"(b[1]));
}
__device__ __forceinline__ uint32_t mulh2(uint32_t a, uint32_t s) {
    __half2 r = __hmul2(*(__half2*)&a, *(__half2*)&s);
    return *(uint32_t*)&r;
}

// ---------------- loaders: ptr8(r, kh) -> gmem pointer to 8 halves ----------------
struct PlainLd {
    const __half* __restrict__ A; int K;
    static constexpr bool scaled = false;
    __device__ __forceinline__ const __half* ptr8(int r, int k) const {
        return A + (long)r * K + k;
    }
    __device__ __forceinline__ float rowscale(int, int) const { return 1.f; }
};
struct GatherLd {   // [x[i0[r]], x[i1[r]], ea[r]]
    const __half* __restrict__ x;
    const int* __restrict__ i0;
    const int* __restrict__ i1;
    const __half* __restrict__ third;
    static constexpr bool scaled = false;
    __device__ __forceinline__ const __half* ptr8(int r, int k) const {
        if (k < 128) return x + (long)i0[r] * 128 + k;
        if (k < 256) return x + (long)i1[r] * 128 + (k - 128);
        return third + (long)r * 128 + (k - 256);
    }
    __device__ __forceinline__ float rowscale(int, int) const { return 1.f; }
};
struct SortGatherLd {   // sorted edge order: [x[dst_s], x[src_s], ea[perm]]
    const __half* __restrict__ x;
    const int* __restrict__ dsts;
    const int* __restrict__ srcs;
    const int* __restrict__ perm;
    const __half* __restrict__ ea;
    static constexpr bool scaled = false;
    __device__ __forceinline__ const __half* ptr8(int r, int k) const {
        if (k < 128) return x + (long)dsts[r] * 128 + k;
        if (k < 256) return x + (long)srcs[r] * 128 + (k - 128);
        return ea + (long)perm[r] * 128 + (k - 256);
    }
    __device__ __forceinline__ float rowscale(int, int) const { return 1.f; }
};
struct PostLd {   // [x, agg, agg*amp, agg*att]
    const __half* __restrict__ x;
    const __half* __restrict__ mean;
    const __half* __restrict__ mn;
    const __half* __restrict__ mx;
    const __half* __restrict__ sd;
    const float* __restrict__ amp;
    const float* __restrict__ att;
    static constexpr bool scaled = true;
    __device__ __forceinline__ const __half* ptr8(int r, int k) const {
        if (k < 128) return x + (long)r * 128 + k;
        int rem = (k - 128) & 511;
        int a   = rem >> 7;
        int c   = rem & 127;
        const __half* base = (a == 0) ? mean : (a == 1) ? mn : (a == 2) ? mx : sd;
        return base + (long)r * 128 + c;
    }
    __device__ __forceinline__ float rowscale(int r, int k) const {
        if (k < 128) return 1.f;
        int grp = (k - 128) >> 9;
        return (grp == 1) ? amp[r] : (grp == 2) ? att[r] : 1.f;
    }
};

// ---------------- epilogues ----------------
struct StoreF {
    float* __restrict__ o;
    __device__ __forceinline__ void pair(int r, int c, float v0, float v1) const {
        *(float2*)(o + (long)r * 128 + c) = make_float2(v0, v1);
    }
};
struct StoreFH {
    float* __restrict__ o;
    __half* __restrict__ oh;
    __device__ __forceinline__ void pair(int r, int c, float v0, float v1) const {
        *(float2*)(o + (long)r * 128 + c) = make_float2(v0, v1);
        *(__half2*)(oh + (long)r * 128 + c) = __floats2half2_rn(v0, v1);
    }
};
struct ReluH {
    __half* __restrict__ oh;
    __device__ __forceinline__ void pair(int r, int c, float v0, float v1) const {
        *(__half2*)(oh + (long)r * 128 + c) = __floats2half2_rn(fmaxf(v0, 0.f), fmaxf(v1, 0.f));
    }
};
struct EaEp {   // ea += v/2, refresh fp16 mirror
    float* __restrict__ ea;
    __half* __restrict__ eah;
    __device__ __forceinline__ void pair(int r, int c, float v0, float v1) const {
        long i = (long)r * 128 + c;
        float2 cur = *(float2*)(ea + i);
        cur.x += 0.5f * v0; cur.y += 0.5f * v1;
        *(float2*)(ea + i) = cur;
        *(__half2*)(eah + i) = __floats2half2_rn(cur.x, cur.y);
    }
};

// ---------------- weight prep: fragment-ordered fp16 pairs ----------------
// layout [c][s][n][t][bi]; k_base = c*32 + s*16 + bi*8 + t*2; pair (k_base, k_base+1)
__global__ void k_prep_w(const float* __restrict__ W, uint32_t* __restrict__ Wp, int nu) {
    int i = blockIdx.x * blockDim.x + threadIdx.x;
    if (i < nu) {
        int bi = i & 1, t = (i >> 1) & 3, n = (i >> 3) & 127, s = (i >> 10) & 1, c = i >> 11;
        int k = c * 32 + s * 16 + bi * 8 + t * 2;
        __half2 v = __floats2half2_rn(W[(long)k * 128 + n], W[(long)(k + 1) * 128 + n]);
        Wp[i] = *(uint32_t*)&v;
    }
}
__global__ void k_prep_w2(const float* __restrict__ W0, const float* __restrict__ W1,
                          int ksplit, uint32_t* __restrict__ Wp, int nu) {
    int i = blockIdx.x * blockDim.x + threadIdx.x;
    if (i < nu) {
        int bi = i & 1, t = (i >> 1) & 3, n = (i >> 3) & 127, s = (i >> 10) & 1, c = i >> 11;
        int k = c * 32 + s * 16 + bi * 8 + t * 2;
        float a = (k     < ksplit) ? W0[(long)k * 128 + n]       : W1[(long)(k - ksplit) * 128 + n];
        float b = (k + 1 < ksplit) ? W0[(long)(k + 1) * 128 + n] : W1[(long)(k + 1 - ksplit) * 128 + n];
        __half2 v = __floats2half2_rn(a, b);
        Wp[i] = *(uint32_t*)&v;
    }
}
__global__ void k_tohalf(const float* __restrict__ s, __half* __restrict__ d, int n) {
    int i = blockIdx.x * blockDim.x + threadIdx.x;
    if (i < n) d[i] = __float2half_rn(s[i]);
}

// ---------------- composite bias builders ----------------
__global__ void k_comp_pre_b(const float* __restrict__ eB, const float* __restrict__ pW,
                             const float* __restrict__ pB, float* __restrict__ cb) {
    int n = threadIdx.x;
    float s = pB[n];
    for (int j = 0; j < 128; j++) s += eB[j] * pW[(long)(256 + j) * 128 + n];
    cb[n] = s;
}
__global__ void k_comp_post_b(const float* __restrict__ poB, const float* __restrict__ lW,
                              const float* __restrict__ lB, float* __restrict__ cb) {
    int n = threadIdx.x;
    float s = lB[n];
    for (int j = 0; j < 128; j++) s += poB[j] * lW[(long)j * 128 + n];
    cb[n] = s;
}
__global__ void k_zero_zb() { g_zb[threadIdx.x] = 0.f; }

// ---------------- fp16 tensor-core GEMM: out[M,128] = A[M,K] @ W[K,128] + b ----------------
// 128x128 CTA tile, 256 threads = 8 warps (4M x 2N), warp tile 32x64.
// mma.sync m16n8k16 f16->f32. K chunk = 32 halves (2 ksteps), 3-stage cp.async.
#define KT 32
#define NSTG 3
#define APH 40   // A pitch in halves

template <typename Loader, typename Epi>
__global__ void __launch_bounds__(256, 2) gemm_mma(
    Loader ld, Epi ep,
    const uint32_t* __restrict__ Wp, const float* __restrict__ bias,
    int M, int K)
{
    __shared__ __half  As[NSTG][128 * APH];
    __shared__ uint32_t Ws[NSTG][2048];
    const int tid  = threadIdx.x;
    const int lane = tid & 31;
    const int wid  = tid >> 5;
    const int wm   = wid & 3;
    const int wn   = wid >> 2;
    const int gid  = lane >> 2;
    const int tid4 = lane & 3;
    const int row0 = blockIdx.x * 128;

    const int sr0 = tid >> 2,  sq0 = tid & 3;
    const int sr1 = sr0 + 64;

    const uint32_t sA = smem_u32(&As[0][0]);
    const uint32_t sW = smem_u32(&Ws[0][0]);

    float acc[2][8][4];
#pragma unroll
    for (int mt = 0; mt < 2; mt++)
#pragma unroll
        for (int nt = 0; nt < 8; nt++)
#pragma unroll
            for (int i = 0; i < 4; i++) acc[mt][nt][i] = 0.f;

    const int nch = K / KT;

    auto stage = [&](int buf, int ch) {
        int k0 = ch * KT;
        uint32_t a_base = sA + buf * (128 * APH * 2);
        uint32_t w_base = sW + buf * 8192;
        int g0 = row0 + sr0, g1 = row0 + sr1;
        bool v0 = g0 < M, v1 = g1 < M;
        cp16(a_base + (sr0 * APH + sq0 * 8) * 2, ld.ptr8(v0 ? g0 : 0, k0 + sq0 * 8), v0);
        cp16(a_base + (sr1 * APH + sq0 * 8) * 2, ld.ptr8(v1 ? g1 : 0, k0 + sq0 * 8), v1);
        const char* wsrc = (const char*)(Wp + (long)ch * 2048);
        cp16(w_base + tid * 16,         wsrc + tid * 16,         true);
        cp16(w_base + (tid + 256) * 16, wsrc + (tid + 256) * 16, true);
        cp_commit();
    };

    int ncommit = 0;
    stage(0, 0); ncommit++;
    if (nch > 1) { stage(1, 1); ncommit++; }

    for (int ch = 0; ch < nch; ch++) {
        const int buf = ch % NSTG;
        const int k0 = ch * KT;
        if (ch + 2 < nch) { stage((ch + 2) % NSTG, ch + 2); ncommit++; }
        int allow = ncommit - ch - 1;
        if (allow >= 2)      asm volatile("cp.async.wait_group 2;" ::: "memory");
        else if (allow == 1) asm volatile("cp.async.wait_group 1;" ::: "memory");
        else                 asm volatile("cp.async.wait_group 0;" ::: "memory");
        __syncthreads();

        uint32_t rsh[2][2];
        if constexpr (Loader::scaled) {
#pragma unroll
            for (int mt = 0; mt < 2; mt++) {
                int m0 = row0 + wm * 32 + mt * 16;
                int rA = m0 + gid, rB = m0 + 8 + gid;
                __half2 hA = __float2half2_rn(ld.rowscale(rA < M ? rA : 0, k0));
                __half2 hB = __float2half2_rn(ld.rowscale(rB < M ? rB : 0, k0));
                rsh[mt][0] = *(uint32_t*)&hA;
                rsh[mt][1] = *(uint32_t*)&hB;
            }
        }

        const __half* Ab = &As[buf][0];
        const uint32_t* Wb = &Ws[buf][0];
#pragma unroll
        for (int s = 0; s < 2; s++) {    // 2 x k16 steps
            uint32_t a[2][4];
#pragma unroll
            for (int mt = 0; mt < 2; mt++) {
                int m0 = wm * 32 + mt * 16;
                a[mt][0] = *(const uint32_t*)(Ab + (m0 + gid)     * APH + s * 16 + 2 * tid4);
                a[mt][1] = *(const uint32_t*)(Ab + (m0 + 8 + gid) * APH + s * 16 + 2 * tid4);
                a[mt][2] = *(const uint32_t*)(Ab + (m0 + gid)     * APH + s * 16 + 8 + 2 * tid4);
                a[mt][3] = *(const uint32_t*)(Ab + (m0 + 8 + gid) * APH + s * 16 + 8 + 2 * tid4);
                if constexpr (Loader::scaled) {
                    a[mt][0] = mulh2(a[mt][0], rsh[mt][0]);
                    a[mt][1] = mulh2(a[mt][1], rsh[mt][1]);
                    a[mt][2] = mulh2(a[mt][2], rsh[mt][0]);
                    a[mt][3] = mulh2(a[mt][3], rsh[mt][1]);
                }
            }
            uint32_t b[8][2];
#pragma unroll
            for (int nt = 0; nt < 8; nt++) {
                int n = wn * 64 + nt * 8 + gid;
                uint2 v = *(const uint2*)(Wb + (long)s * 1024 + (n * 4 + tid4) * 2);
                b[nt][0] = v.x;
                b[nt][1] = v.y;
            }
#pragma unroll
            for (int mt = 0; mt < 2; mt++)
#pragma unroll
                for (int nt = 0; nt < 8; nt++)
                    mma_f16(acc[mt][nt], a[mt], b[nt]);
        }
        __syncthreads();
    }

    float bv[8][2];
#pragma unroll
    for (int nt = 0; nt < 8; nt++) {
        int c = wn * 64 + nt * 8 + 2 * tid4;
        bv[nt][0] = bias[c];
        bv[nt][1] = bias[c + 1];
    }
#pragma unroll
    for (int mt = 0; mt < 2; mt++) {
        int rA = row0 + wm * 32 + mt * 16 + gid;
        int rB = rA + 8;
#pragma unroll
        for (int nt = 0; nt < 8; nt++) {
            int c = wn * 64 + nt * 8 + 2 * tid4;
            if (rA < M) ep.pair(rA, c, acc[mt][nt][0] + bv[nt][0], acc[mt][nt][1] + bv[nt][1]);
            if (rB < M) ep.pair(rB, c, acc[mt][nt][2] + bv[nt][0], acc[mt][nt][3] + bv[nt][1]);
        }
    }
}

// ---------------- CSR build (parallel scan) ----------------
__global__ void k_zero_deg() {
    int i = blockIdx.x * blockDim.x + threadIdx.x;
    if (i < NN) g_deg[i] = 0;
}
__global__ void k_count_deg(const int* __restrict__ dst) {
    int e = blockIdx.x * blockDim.x + threadIdx.x;
    if (e < EE) atomicAdd(&g_deg[dst[e]], 1);
}
__global__ void k_scan1() {
    __shared__ int s[256];
    int b = blockIdx.x, t = threadIdx.x, i = b * 256 + t;
    int v = (i < NN) ? g_deg[i] : 0;
    s[t] = v; __syncthreads();
    for (int d = 1; d < 256; d <<= 1) {
        int x = (t >= d) ? s[t - d] : 0;
        __syncthreads();
        s[t] += x;
        __syncthreads();
    }
    if (i < NN) g_rowptr[i + 1] = s[t];
    if (t == 255) g_bsum[b] = s[255];
}
__global__ void k_scan2(int nblk) {
    __shared__ int s[256];
    int t = threadIdx.x;
    int v = (t < nblk) ? g_bsum[t] : 0;
    s[t] = v; __syncthreads();
    for (int d = 1; d < 256; d <<= 1) {
        int x = (t >= d) ? s[t - d] : 0;
        __syncthreads();
        s[t] += x;
        __syncthreads();
    }
    g_bexc[t] = s[t] - v;
}
__global__ void k_scan3() {
    int b = blockIdx.x, t = threadIdx.x, i = b * 256 + t;
    if (i < NN) {
        int off = g_bexc[b];
        int incl = g_rowptr[i + 1] + off;
        g_rowptr[i + 1] = incl;
        g_cur[i] = incl - g_deg[i];
    }
    if (b == 0 && t == 0) g_rowptr[0] = 0;
}
__global__ void k_scatter(const int* __restrict__ src, const int* __restrict__ dst) {
    int e = blockIdx.x * blockDim.x + threadIdx.x;
    if (e < EE) {
        int n = dst[e];
        int pos = atomicAdd(&g_cur[n], 1);
        g_perm[pos] = e;
        g_dsts[pos] = n;
        g_srcs[pos] = src[e];
    }
}
__global__ void k_amp_att(const float* __restrict__ adl) {
    int i = blockIdx.x * blockDim.x + threadIdx.x;
    if (i < NN) {
        float d = fmaxf((float)g_deg[i], 1.f);
        float lg = logf(d + 1.f);
        float a = adl[0];
        g_amp[i] = lg / a;
        g_att[i] = a / lg;
    }
}

// ---------------- segmented reduction -> fp16 agg arrays ----------------
__global__ void k_seg_reduce(const float* __restrict__ h) {
    int n = blockIdx.x;
    int c = threadIdx.x;
    int s = g_rowptr[n], e = g_rowptr[n + 1];
    float sum = 0.f, sq = 0.f;
    float mn = __int_as_float(0x7f800000);
    float mx = __int_as_float(0xff800000);
    for (int i = s; i < e; i++) {
        float v = h[(long)i * 128 + c];
        sum += v; sq += v * v;
        mn = fminf(mn, v); mx = fmaxf(mx, v);
    }
    int d = e - s;
    float degc = fmaxf((float)d, 1.f);
    float m = sum / degc;
    float var = sq / degc - m * m;
    long o = (long)n * 128 + c;
    g_s1h[o] = __float2half_rn(m);
    g_s2h[o] = __float2half_rn(sqrtf(fmaxf(var, 0.f) + 1e-5f));
    g_mnh[o] = __float2half_rn(d ? mn : 0.f);
    g_mxh[o] = __float2half_rn(d ? mx : 0.f);
}

// ---------------- BN + residual ----------------
__global__ void k_zero_bn() {
    int c = threadIdx.x;
    g_bnsum[c] = 0.f;
    g_bnsq[c] = 0.f;
}
__global__ void k_bn_stats(const float* __restrict__ o) {
    int c = threadIdx.x;
    float s = 0.f, s2 = 0.f;
    for (int r = blockIdx.x; r < NN; r += gridDim.x) {
        float v = o[(long)r * 128 + c];
        s += v; s2 += v * v;
    }
    atomicAdd(&g_bnsum[c], s);
    atomicAdd(&g_bnsq[c], s2);
}
__global__ void k_bn_fin() {
    int c = threadIdx.x;
    float mu = g_bnsum[c] / (float)NN;
    float var = g_bnsq[c] / (float)NN - mu * mu;
    g_bnmu[c] = mu;
    g_bnrstd[c] = rsqrtf(var + 1e-5f);
}
__global__ void k_apply(const float* __restrict__ bng, const float* __restrict__ bnb,
                        float* __restrict__ xout) {
    long i = (long)blockIdx.x * blockDim.x + threadIdx.x;
    if (i < (long)NN * HH) {
        int c = (int)(i & 127);
        float v = bng[c] * (g_lin[i] - g_bnmu[c]) * g_bnrstd[c] + bnb[c];
        float nx = (g_x[i] + fmaxf(v, 0.f)) * 0.5f;
        g_x[i] = nx;
        g_x16[i] = __float2half_rn(nx);
        if (xout) xout[i] = nx;
    }
}

// ---------------- launch ----------------
extern "C" void kernel_launch(void* const* d_in, const int* in_sizes, int n_in,
                              void* d_out, int out_size) {
    const float* x_in       = (const float*)d_in[0];
    const int*   eidx       = (const int*)  d_in[1];
    const float* edge_attr  = (const float*)d_in[2];
    const float* pos_attr   = (const float*)d_in[4];
    const float* neg_attr   = (const float*)d_in[6];
    const float* avg_dl     = (const float*)d_in[7];
    const float* node_emb_w = (const float*)d_in[8];
    const float* node_emb_b = (const float*)d_in[9];
    const float* edge_emb_w = (const float*)d_in[10];
    const float* edge_emb_b = (const float*)d_in[11];
    const float* eenc_w     = (const float*)d_in[12];
    const float* eenc_b     = (const float*)d_in[13];
    const float* pre_w      = (const float*)d_in[14];
    const float* pre_b      = (const float*)d_in[15];
    const float* post_w     = (const float*)d_in[16];
    const float* post_b     = (const float*)d_in[17];
    const float* lin_w      = (const float*)d_in[18];
    const float* lin_b      = (const float*)d_in[19];
    const float* emlp_w1    = (const float*)d_in[20];
    const float* emlp_b1    = (const float*)d_in[21];
    const float* emlp_w2    = (const float*)d_in[22];
    const float* emlp_b2    = (const float*)d_in[23];
    const float* bn_g       = (const float*)d_in[24];
    const float* bn_b       = (const float*)d_in[25];

    const int* src = eidx;
    const int* dst = eidx + EE;

    float* out     = (float*)d_out;
    float* pos_out = out + (long)NN * HH;
    float* neg_out = pos_out + (long)EPP * HH;

    float *p_x, *p_ea, *p_h, *p_lin, *p_amp, *p_att, *p_cw, *p_cb, *p_cb2, *p_zb;
    __half *p_x16, *p_ea16, *p_upd16, *p_s1h, *p_s2h, *p_mnh, *p_mxh;
    __half *p_in16, *p_xin16, *p_pos16, *p_neg16, *p_wh16;
    uint32_t *p_wt, *p_wt2;
    int *p_perm, *p_srcs, *p_dsts;
    cudaGetSymbolAddress((void**)&p_x, g_x);
    cudaGetSymbolAddress((void**)&p_x16, g_x16);
    cudaGetSymbolAddress((void**)&p_ea, g_ea);
    cudaGetSymbolAddress((void**)&p_ea16, g_ea16);
    cudaGetSymbolAddress((void**)&p_h, g_h);
    cudaGetSymbolAddress((void**)&p_upd16, g_upd16);
    cudaGetSymbolAddress((void**)&p_lin, g_lin);
    cudaGetSymbolAddress((void**)&p_s1h, g_s1h);
    cudaGetSymbolAddress((void**)&p_s2h, g_s2h);
    cudaGetSymbolAddress((void**)&p_mnh, g_mnh);
    cudaGetSymbolAddress((void**)&p_mxh, g_mxh);
    cudaGetSymbolAddress((void**)&p_in16, g_in16);
    cudaGetSymbolAddress((void**)&p_xin16, g_xin16);
    cudaGetSymbolAddress((void**)&p_pos16, g_pos16);
    cudaGetSymbolAddress((void**)&p_neg16, g_neg16);
    cudaGetSymbolAddress((void**)&p_wh16, g_wh16);
    cudaGetSymbolAddress((void**)&p_amp, g_amp);
    cudaGetSymbolAddress((void**)&p_att, g_att);
    cudaGetSymbolAddress((void**)&p_cw, g_cw);
    cudaGetSymbolAddress((void**)&p_cb, g_cb);
    cudaGetSymbolAddress((void**)&p_cb2, g_cb2);
    cudaGetSymbolAddress((void**)&p_zb, g_zb);
    cudaGetSymbolAddress((void**)&p_wt, g_wt);
    cudaGetSymbolAddress((void**)&p_wt2, g_wt2);
    cudaGetSymbolAddress((void**)&p_perm, g_perm);
    cudaGetSymbolAddress((void**)&p_srcs, g_srcs);
    cudaGetSymbolAddress((void**)&p_dsts, g_dsts);

    const int NB_N  = (NN + 127) / 128;
    const int NB_E  = (EE + 127) / 128;
    const int NB_EP = (EPP + 127) / 128;
    const int TPB = 256;
    const int GB_N = (NN + TPB - 1) / TPB;   // 196
    const int GB_E = (EE + TPB - 1) / TPB;
    const long NH = (long)NN * HH;
    const int GB_NH = (int)((NH + TPB - 1) / TPB);

    auto prepW = [&](const float* w, int K, uint32_t* dstp) {
        int nu = (K / 32) * 2048;
        k_prep_w<<<(nu + 255) / 256, 256>>>(w, dstp, nu);
    };
    auto tohalf = [&](const float* s, __half* d, int n) {
        k_tohalf<<<(n + 255) / 256, 256>>>(s, d, n);
    };

    // one-time: CSR, amp/att, input conversions
    k_zero_zb<<<1, HH>>>();
    k_zero_deg<<<GB_N, TPB>>>();
    k_count_deg<<<GB_E, TPB>>>(dst);
    k_scan1<<<GB_N, 256>>>();
    k_scan2<<<1, 256>>>(GB_N);
    k_scan3<<<GB_N, 256>>>();
    k_scatter<<<GB_E, TPB>>>(src, dst);
    k_amp_att<<<GB_N, TPB>>>(avg_dl);

    tohalf(x_in, p_xin16, NN * FF);
    tohalf(edge_attr, p_in16, EE * EDD);
    tohalf(pos_attr, p_pos16, EPP * EDD);
    tohalf(neg_attr, p_neg16, EPP * EDD);

    // embeddings
    prepW(node_emb_w, FF, p_wt);
    gemm_mma<<<NB_N, 256>>>(PlainLd{p_xin16, FF}, StoreFH{p_x, p_x16}, p_wt, node_emb_b, NN, FF);
    prepW(edge_emb_w, EDD, p_wt);
    gemm_mma<<<NB_E, 256>>>(PlainLd{p_in16, EDD}, StoreFH{p_ea, p_ea16}, p_wt, edge_emb_b, EE, EDD);
    gemm_mma<<<NB_EP, 256>>>(PlainLd{p_pos16, EDD}, StoreF{pos_out}, p_wt, edge_emb_b, EPP, EDD);
    gemm_mma<<<NB_EP, 256>>>(PlainLd{p_neg16, EDD}, StoreF{neg_out}, p_wt, edge_emb_b, EPP, EDD);

    for (int l = 0; l < LL; l++) {
        const float* eW  = eenc_w  + (long)l * HH * HH;
        const float* eB  = eenc_b  + (long)l * HH;
        const float* pW  = pre_w   + (long)l * 3 * HH * HH;
        const float* pB  = pre_b   + (long)l * HH;
        const float* poW = post_w  + (long)l * 13 * HH * HH;
        const float* poB = post_b  + (long)l * HH;
        const float* lW  = lin_w   + (long)l * HH * HH;
        const float* lB  = lin_b   + (long)l * HH;
        const float* m1W = emlp_w1 + (long)l * 3 * HH * HH;
        const float* m1B = emlp_b1 + (long)l * HH;
        const float* m2W = emlp_w2 + (long)l * HH * HH;
        const float* m2B = emlp_b2 + (long)l * HH;
        const float* bG  = bn_g    + (long)l * HH;
        const float* bB  = bn_b    + (long)l * HH;

        k_zero_bn<<<1, HH>>>();

        // --- composite pre weight via fp16 GEMM: cw_tail = eW @ pW3 ---
        const float* pW3 = pW + 256 * 128;
        tohalf(eW, p_wh16, HH * HH);
        prepW(pW3, HH, p_wt2);
        gemm_mma<<<1, 256>>>(PlainLd{p_wh16, HH}, StoreF{p_cw}, p_wt2, p_zb, 128, HH);
        k_comp_pre_b<<<1, 128>>>(eB, pW, pB, p_cb);
        {
            int nu = (3 * HH / 32) * 2048;
            k_prep_w2<<<(nu + 255) / 256, 256>>>(pW, p_cw, 256, p_wt, nu);
        }
        // h(sorted) = [x[dst_s], x[src_s], ea[perm]] @ W' + b'
        gemm_mma<<<NB_E, 256>>>(SortGatherLd{p_x16, p_dsts, p_srcs, p_perm, p_ea16},
                                StoreF{p_h}, p_wt, p_cb, EE, 3 * HH);
        k_seg_reduce<<<NN, 128>>>(p_h);

        // --- composite post+lin weight: cw = poW @ lW ---
        tohalf(poW, p_wh16, 13 * HH * HH);
        prepW(lW, HH, p_wt2);
        gemm_mma<<<13, 256>>>(PlainLd{p_wh16, HH}, StoreF{p_cw}, p_wt2, p_zb, 13 * HH, HH);
        k_comp_post_b<<<1, 128>>>(poB, lW, lB, p_cb2);
        prepW(p_cw, 13 * HH, p_wt);
        // out = [x, agg, agg*amp, agg*att] @ (poW@lW) + b''
        gemm_mma<<<NB_N, 256>>>(PostLd{p_x16, p_s1h, p_mnh, p_mxh, p_s2h, p_amp, p_att},
                                StoreF{p_lin}, p_wt, p_cb2, NN, 13 * HH);

        k_bn_stats<<<256, HH>>>(p_lin);
        k_bn_fin<<<1, HH>>>();
        k_apply<<<GB_NH, TPB>>>(bG, bB, (l == LL - 1) ? out : (float*)nullptr);

        // upd = relu([x[src], x[dst], ea] @ emlp_w1 + b1)
        prepW(m1W, 3 * HH, p_wt);
        gemm_mma<<<NB_E, 256>>>(GatherLd{p_x16, src, dst, p_ea16},
                                ReluH{p_upd16}, p_wt, m1B, EE, 3 * HH);
        // ea = ea + (upd @ emlp_w2 + b2) / 2
        prepW(m2W, HH, p_wt);
        gemm_mma<<<NB_E, 256>>>(PlainLd{p_upd16, HH}, EaEp{p_ea, p_ea16}, p_wt, m2B, EE, HH);
    }
}